// round 1
// baseline (speedup 1.0000x reference)
#include <cuda_runtime.h>
#include <math.h>

#define NB 2
#define NL 2048
#define NE 1024
#define NH 16
#define NHD 64
#define NM (NB*NL)   /* 4096 rows of x */

// Scratch (no allocation allowed) — 4 x 16MB fp32
__device__ float g_q[NB*NH*NL*NHD];
__device__ float g_k[NB*NH*NL*NHD];
__device__ float g_v[NB*NH*NL*NHD];
__device__ float g_attn[NB*NL*NE];

// ---------------------------------------------------------------------------
// GEMM: C[m,n] = sum_k A[m,k] * W[n,k] + bias[n]   (A: [M,K] rm, W: [N,K] rm)
// MODE 0: write [b,h,l,d] (v path)
// MODE 1: apply RoPE, write [b,h,l,d] (q/k path)
// MODE 2: plain write [m,n] (output projection)
// Tiles: BM=BN=128, BK=8, 256 threads, 8x8 per thread, double-buffered smem.
// ---------------------------------------------------------------------------
template<int MODE>
__global__ __launch_bounds__(256, 2)
void gemm_kernel(const float* __restrict__ A, const float* __restrict__ W,
                 const float* __restrict__ bias, float* __restrict__ out)
{
    const int K = NE, N = NE;
    __shared__ float As[2][8][132];   // [k][m], padded
    __shared__ float Bs[2][8][132];   // [k][n], padded

    const int tid = threadIdx.x;
    const int tx = tid & 15, ty = tid >> 4;
    const int m0 = blockIdx.y * 128, n0 = blockIdx.x * 128;

    // loader mapping: each thread loads one float4 of A and one of W per tile
    const int lr = tid >> 1;           // 0..127
    const int lk = (tid & 1) * 4;      // 0 or 4
    const float* Ap = A + (size_t)(m0 + lr) * K + lk;
    const float* Wp = W + (size_t)(n0 + lr) * K + lk;

    float4 fa = *(const float4*)Ap;
    float4 fb = *(const float4*)Wp;
    As[0][lk+0][lr] = fa.x; As[0][lk+1][lr] = fa.y; As[0][lk+2][lr] = fa.z; As[0][lk+3][lr] = fa.w;
    Bs[0][lk+0][lr] = fb.x; Bs[0][lk+1][lr] = fb.y; Bs[0][lk+2][lr] = fb.z; Bs[0][lk+3][lr] = fb.w;
    __syncthreads();

    float acc[8][8];
    #pragma unroll
    for (int i = 0; i < 8; i++)
        #pragma unroll
        for (int j = 0; j < 8; j++) acc[i][j] = 0.f;

    const int nT = K / 8;   // 128
    for (int t = 0; t < nT; t++) {
        const int buf = t & 1;
        if (t + 1 < nT) {
            fa = *(const float4*)(Ap + (t+1)*8);
            fb = *(const float4*)(Wp + (t+1)*8);
        }
        #pragma unroll
        for (int k = 0; k < 8; k++) {
            float a[8], b[8];
            *(float4*)&a[0] = *(const float4*)&As[buf][k][ty*8];
            *(float4*)&a[4] = *(const float4*)&As[buf][k][ty*8 + 4];
            *(float4*)&b[0] = *(const float4*)&Bs[buf][k][tx*8];
            *(float4*)&b[4] = *(const float4*)&Bs[buf][k][tx*8 + 4];
            #pragma unroll
            for (int i = 0; i < 8; i++)
                #pragma unroll
                for (int j = 0; j < 8; j++)
                    acc[i][j] = fmaf(a[i], b[j], acc[i][j]);
        }
        if (t + 1 < nT) {
            const int nb = buf ^ 1;
            As[nb][lk+0][lr] = fa.x; As[nb][lk+1][lr] = fa.y; As[nb][lk+2][lr] = fa.z; As[nb][lk+3][lr] = fa.w;
            Bs[nb][lk+0][lr] = fb.x; Bs[nb][lk+1][lr] = fb.y; Bs[nb][lk+2][lr] = fb.z; Bs[nb][lk+3][lr] = fb.w;
        }
        __syncthreads();
    }

    // --- epilogue ---
    #pragma unroll
    for (int i = 0; i < 8; i++) {
        const int m = m0 + ty*8 + i;
        const int bidx = m >> 11;          // m / 2048
        const int l    = m & (NL - 1);

        if (MODE == 2) {
            #pragma unroll
            for (int j = 0; j < 8; j++) {
                const int n = n0 + tx*8 + j;
                out[(size_t)m * N + n] = acc[i][j] + bias[n];
            }
        } else if (MODE == 0) {
            #pragma unroll
            for (int j = 0; j < 8; j++) {
                const int n = n0 + tx*8 + j;
                const int h = n >> 6, d = n & 63;
                out[((((size_t)bidx*NH + h)*NL) + l)*NHD + d] = acc[i][j] + bias[n];
            }
        } else { // MODE 1: RoPE (interleaved pairs)
            #pragma unroll
            for (int j = 0; j < 8; j += 2) {
                const int n = n0 + tx*8 + j;
                const int h = n >> 6, d = n & 63;       // d is even
                const float v0 = acc[i][j]   + bias[n];
                const float v1 = acc[i][j+1] + bias[n+1];
                // inv_freq = 10000^(-(d/2)/32) = exp2(-(d/2)/32 * log2(10000))
                const float fi = (float)(d >> 1);
                const float invf = exp2f(fi * (-13.287712379549449f / 32.0f));
                const float ang = (float)l * invf;
                float sn, cs;
                sincosf(ang, &sn, &cs);
                const size_t base = ((((size_t)bidx*NH + h)*NL) + l)*NHD + d;
                out[base]     = v0*cs - v1*sn;
                out[base + 1] = v1*cs + v0*sn;
            }
        }
    }
}

// ---------------------------------------------------------------------------
// Flash attention: one block = 64 query rows of one (b,h). 256 threads.
// Online softmax, full (non-causal) attention over L=2048 keys, HD=64.
// smem: Qt[d][row], Kt[d][key], Vs[key][d], Ps[row][key], all stride 68.
// Thread (tx,ty): rows ty*4..+3, key-cols / out-dims tx*4..+3.
// Row stats reduced across the 16 tx lanes via half-warp shfl.
// Output written [b, l, h, d] so the final projection reads it row-major.
// ---------------------------------------------------------------------------
__global__ __launch_bounds__(256, 2)
void attn_kernel(const float* __restrict__ q, const float* __restrict__ k,
                 const float* __restrict__ v, float* __restrict__ out)
{
    extern __shared__ float smbuf[];
    float (*Qt)[68] = (float(*)[68])(smbuf);
    float (*Kt)[68] = (float(*)[68])(smbuf + 64*68);
    float (*Vs)[68] = (float(*)[68])(smbuf + 2*64*68);
    float (*Ps)[68] = (float(*)[68])(smbuf + 3*64*68);

    const int tid = threadIdx.x;
    const int tx = tid & 15, ty = tid >> 4;
    const int q0 = blockIdx.x * 64;
    const int bh = blockIdx.y;
    const int b = bh >> 4, h = bh & 15;
    const float* qp = q + (size_t)bh * NL * NHD;
    const float* kp = k + (size_t)bh * NL * NHD;
    const float* vp = v + (size_t)bh * NL * NHD;

    // Load Q tile transposed: Qt[d][row]
    for (int e = tid; e < 1024; e += 256) {
        const int r = e >> 4, d4 = (e & 15) * 4;
        float4 val = *(const float4*)&qp[(size_t)(q0 + r)*NHD + d4];
        Qt[d4+0][r] = val.x; Qt[d4+1][r] = val.y; Qt[d4+2][r] = val.z; Qt[d4+3][r] = val.w;
    }

    float m_i[4], l_i[4], oacc[4][4];
    #pragma unroll
    for (int i = 0; i < 4; i++) {
        m_i[i] = -1e30f; l_i[i] = 0.f;
        #pragma unroll
        for (int j = 0; j < 4; j++) oacc[i][j] = 0.f;
    }

    for (int kt = 0; kt < NL; kt += 64) {
        __syncthreads();   // prev iter's Vs/Ps reads (and Qt load) complete
        for (int e = tid; e < 1024; e += 256) {
            const int r = e >> 4, d4 = (e & 15) * 4;
            float4 kv = *(const float4*)&kp[(size_t)(kt + r)*NHD + d4];
            Kt[d4+0][r] = kv.x; Kt[d4+1][r] = kv.y; Kt[d4+2][r] = kv.z; Kt[d4+3][r] = kv.w;
            float4 vv = *(const float4*)&vp[(size_t)(kt + r)*NHD + d4];
            *(float4*)&Vs[r][d4] = vv;
        }
        __syncthreads();

        // S = Q K^T (4x4 microtile)
        float s[4][4];
        #pragma unroll
        for (int i = 0; i < 4; i++)
            #pragma unroll
            for (int j = 0; j < 4; j++) s[i][j] = 0.f;

        #pragma unroll 16
        for (int d = 0; d < 64; d++) {
            float qa[4], ka[4];
            *(float4*)qa = *(const float4*)&Qt[d][ty*4];
            *(float4*)ka = *(const float4*)&Kt[d][tx*4];
            #pragma unroll
            for (int i = 0; i < 4; i++)
                #pragma unroll
                for (int j = 0; j < 4; j++)
                    s[i][j] = fmaf(qa[i], ka[j], s[i][j]);
        }

        // Online softmax per row (reduce across tx half-warp groups)
        #pragma unroll
        for (int i = 0; i < 4; i++) {
            #pragma unroll
            for (int j = 0; j < 4; j++) s[i][j] *= 0.125f;   // 1/sqrt(64)
            float rmax = fmaxf(fmaxf(s[i][0], s[i][1]), fmaxf(s[i][2], s[i][3]));
            #pragma unroll
            for (int off = 8; off > 0; off >>= 1)
                rmax = fmaxf(rmax, __shfl_xor_sync(0xffffffffu, rmax, off));
            const float mnew = fmaxf(m_i[i], rmax);
            const float corr = __expf(m_i[i] - mnew);
            m_i[i] = mnew;
            float p[4]; float rsum = 0.f;
            #pragma unroll
            for (int j = 0; j < 4; j++) { p[j] = __expf(s[i][j] - mnew); rsum += p[j]; }
            #pragma unroll
            for (int off = 8; off > 0; off >>= 1)
                rsum += __shfl_xor_sync(0xffffffffu, rsum, off);
            l_i[i] = l_i[i]*corr + rsum;
            #pragma unroll
            for (int j = 0; j < 4; j++) oacc[i][j] *= corr;
            *(float4*)&Ps[ty*4 + i][tx*4] = make_float4(p[0], p[1], p[2], p[3]);
        }
        __syncthreads();

        // O += P @ V (thread owns out-dims tx*4..+3 for rows ty*4..+3)
        #pragma unroll 8
        for (int kk = 0; kk < 64; kk++) {
            float4 vv = *(const float4*)&Vs[kk][tx*4];
            #pragma unroll
            for (int i = 0; i < 4; i++) {
                const float pp = Ps[ty*4 + i][kk];
                oacc[i][0] = fmaf(pp, vv.x, oacc[i][0]);
                oacc[i][1] = fmaf(pp, vv.y, oacc[i][1]);
                oacc[i][2] = fmaf(pp, vv.z, oacc[i][2]);
                oacc[i][3] = fmaf(pp, vv.w, oacc[i][3]);
            }
        }
    }

    // Normalize and write [b, l, h, d]
    #pragma unroll
    for (int i = 0; i < 4; i++) {
        const int l = q0 + ty*4 + i;
        const float inv = 1.f / l_i[i];
        float4 o4 = make_float4(oacc[i][0]*inv, oacc[i][1]*inv,
                                oacc[i][2]*inv, oacc[i][3]*inv);
        *(float4*)&out[(((size_t)b*NL + l)*NH + h)*NHD + tx*4] = o4;
    }
}

// ---------------------------------------------------------------------------
extern "C" void kernel_launch(void* const* d_in, const int* in_sizes, int n_in,
                              void* d_out, int out_size)
{
    (void)in_sizes; (void)n_in; (void)out_size;
    const float* x  = (const float*)d_in[0];
    const float* Wq = (const float*)d_in[1];
    const float* bq = (const float*)d_in[2];
    const float* Wk = (const float*)d_in[3];
    const float* bk = (const float*)d_in[4];
    const float* Wv = (const float*)d_in[5];
    const float* bv = (const float*)d_in[6];
    const float* Wo = (const float*)d_in[7];
    const float* bo = (const float*)d_in[8];

    float *qb, *kb, *vb, *ab;
    cudaGetSymbolAddress((void**)&qb, g_q);
    cudaGetSymbolAddress((void**)&kb, g_k);
    cudaGetSymbolAddress((void**)&vb, g_v);
    cudaGetSymbolAddress((void**)&ab, g_attn);

    dim3 blk(256);
    dim3 grid_g(NE/128, NM/128);   // (8, 32)

    gemm_kernel<1><<<grid_g, blk>>>(x, Wq, bq, qb);
    gemm_kernel<1><<<grid_g, blk>>>(x, Wk, bk, kb);
    gemm_kernel<0><<<grid_g, blk>>>(x, Wv, bv, vb);

    const int smem = 4 * 64 * 68 * (int)sizeof(float);   // 69632 B
    cudaFuncSetAttribute(attn_kernel, cudaFuncAttributeMaxDynamicSharedMemorySize, smem);
    attn_kernel<<<dim3(NL/64, NB*NH), blk, smem>>>(qb, kb, vb, ab);

    gemm_kernel<2><<<grid_g, blk>>>(ab, Wo, bo, (float*)d_out);
}

// round 4
// speedup vs baseline: 1.3862x; 1.3862x over previous
#include <cuda_runtime.h>
#include <cuda_bf16.h>
#include <math.h>
#include <stdint.h>

#define NB 2
#define NL 2048
#define NE 1024
#define NH 16
#define NHD 64
#define NM (NB*NL)   /* 4096 rows */

// ---------------- scratch (__device__ globals; no allocation) ----------------
__device__ float g_q[NB*NH*NL*NHD];
__device__ float g_k[NB*NH*NL*NHD];
__device__ float g_v[NB*NH*NL*NHD];
__device__ __nv_bfloat16 g_xhi[NM*NE];
__device__ __nv_bfloat16 g_xlo[NM*NE];
__device__ __nv_bfloat16 g_whi[4*NE*NE];
__device__ __nv_bfloat16 g_wlo[4*NE*NE];
__device__ __nv_bfloat16 g_ahi[NM*NE];
__device__ __nv_bfloat16 g_alo[NM*NE];

// ---------------- PTX helpers (sm_80-level only; no 'a' features) ----------------
__device__ __forceinline__ uint32_t smem_u32(const void* p) {
    uint32_t a;
    asm("{ .reg .u64 t; cvta.to.shared.u64 t, %1; cvt.u32.u64 %0, t; }" : "=r"(a) : "l"(p));
    return a;
}
__device__ __forceinline__ void cp16(uint32_t s, const void* g) {
    asm volatile("cp.async.cg.shared.global [%0], [%1], 16;" :: "r"(s), "l"(g));
}
__device__ __forceinline__ void cp_commit() { asm volatile("cp.async.commit_group;" ::: "memory"); }
__device__ __forceinline__ void cp_wait2()  { asm volatile("cp.async.wait_group 2;" ::: "memory"); }

__device__ __forceinline__ void ldsm4(uint32_t* r, uint32_t addr) {
    asm volatile("ldmatrix.sync.aligned.m8n8.x4.shared.b16 {%0,%1,%2,%3}, [%4];"
                 : "=r"(r[0]), "=r"(r[1]), "=r"(r[2]), "=r"(r[3]) : "r"(addr));
}
// D(f32) += A(bf16) * B(bf16), m16n8k16
__device__ __forceinline__ void mma16816(float* d, const uint32_t* a, uint32_t b0, uint32_t b1) {
    asm volatile("mma.sync.aligned.m16n8k16.row.col.f32.bf16.bf16.f32 "
                 "{%0,%1,%2,%3}, {%4,%5,%6,%7}, {%8,%9}, {%0,%1,%2,%3};"
                 : "+f"(d[0]), "+f"(d[1]), "+f"(d[2]), "+f"(d[3])
                 : "r"(a[0]), "r"(a[1]), "r"(a[2]), "r"(a[3]), "r"(b0), "r"(b1));
}

// ---------------- split fp32 -> bf16 hi/lo ----------------
__global__ void split_kernel(const float* __restrict__ in,
                             __nv_bfloat16* __restrict__ hi,
                             __nv_bfloat16* __restrict__ lo, int n)
{
    int i = blockIdx.x * blockDim.x + threadIdx.x;
    if (i < n) {
        float v = in[i];
        __nv_bfloat16 h = __float2bfloat16(v);
        hi[i] = h;
        lo[i] = __float2bfloat16(v - __bfloat162float(h));
    }
}

// ---------------------------------------------------------------------------
// HMMA GEMM: D[m,n] = sum_k A[m,k]*B[n,k] + bias[n]
//   A = Ahi+Alo, B = Bhi+Blo (bf16 split); fp32 accum; 3 mma products.
// CTA tile 128x128, 8 warps (4m x 2n), warp tile 32x64, BK=32.
// 4-stage cp.async ring: stage = {Ahi 8K | Alo 8K | Bhi 8K | Blo 8K} = 32KB.
// Tiles stored [row][32 bf16] (64B rows), XOR swizzle chunk^((row>>1)&3).
// MODE 0: [b,h,l,d]   MODE 1: RoPE -> [b,h,l,d]   MODE 2: [m,n]
// ---------------------------------------------------------------------------
template<int MODE>
__global__ __launch_bounds__(256, 1)
void gemm_mma(const __nv_bfloat16* __restrict__ Ahi, const __nv_bfloat16* __restrict__ Alo,
              const __nv_bfloat16* __restrict__ Bhi, const __nv_bfloat16* __restrict__ Blo,
              const float* __restrict__ bias, float* __restrict__ out)
{
    extern __shared__ char smraw[];
    const uint32_t sm0 = smem_u32(smraw);

    const int tid = threadIdx.x;
    const int lane = tid & 31, w = tid >> 5;
    const int wm = w & 3, wn = w >> 2;          // 4 x 2 warp grid
    const int m0 = blockIdx.y * 128, n0 = blockIdx.x * 128;

    auto load_stage = [&](int stage, int buf) {
        const uint32_t base = sm0 + (uint32_t)buf * 32768u;
        const int kc = stage * 32;
        #pragma unroll
        for (int i = tid; i < 512; i += 256) {
            const int row = i >> 2, c = i & 3;
            const int cs = c ^ ((row >> 1) & 3);
            const uint32_t off = (uint32_t)(row * 64 + cs * 16);
            const size_t ga = (size_t)(m0 + row) * NE + kc + c * 8;
            const size_t gb = (size_t)(n0 + row) * NE + kc + c * 8;
            cp16(base +          off, Ahi + ga);
            cp16(base +  8192u + off, Alo + ga);
            cp16(base + 16384u + off, Bhi + gb);
            cp16(base + 24576u + off, Blo + gb);
        }
        cp_commit();
    };

    load_stage(0, 0); load_stage(1, 1); load_stage(2, 2);

    float acc[2][8][4];
    #pragma unroll
    for (int a = 0; a < 2; a++)
        #pragma unroll
        for (int b = 0; b < 8; b++)
            #pragma unroll
            for (int c = 0; c < 4; c++) acc[a][b][c] = 0.f;

    const int NS = NE / 32;   // 32 stages
    for (int t = 0; t < NS; t++) {
        cp_wait2();
        __syncthreads();
        if (t + 3 < NS) load_stage(t + 3, (t + 3) & 3); else cp_commit();

        const uint32_t base = sm0 + (uint32_t)(t & 3) * 32768u;
        #pragma unroll
        for (int s = 0; s < 2; s++) {
            const int chunk = 2 * s + (lane >> 4);
            uint32_t ah[2][4], al[2][4];
            #pragma unroll
            for (int mt = 0; mt < 2; mt++) {
                const int row = wm * 32 + mt * 16 + (lane & 15);
                const int cs = chunk ^ ((row >> 1) & 3);
                const uint32_t a = base + (uint32_t)(row * 64 + cs * 16);
                ldsm4(ah[mt], a);
                ldsm4(al[mt], a + 8192u);
            }
            uint32_t bh[4][4], bl[4][4];
            #pragma unroll
            for (int g = 0; g < 4; g++) {
                const int row = wn * 64 + g * 16 + (lane & 15);
                const int cs = chunk ^ ((row >> 1) & 3);
                const uint32_t a = base + 16384u + (uint32_t)(row * 64 + cs * 16);
                ldsm4(bh[g], a);
                ldsm4(bl[g], a + 8192u);
            }
            #pragma unroll
            for (int mt = 0; mt < 2; mt++)
                #pragma unroll
                for (int g = 0; g < 4; g++)
                    #pragma unroll
                    for (int h2 = 0; h2 < 2; h2++) {
                        float* d = acc[mt][g * 2 + h2];
                        mma16816(d, ah[mt], bh[g][h2], bh[g][h2 + 2]);
                        mma16816(d, ah[mt], bl[g][h2], bl[g][h2 + 2]);
                        mma16816(d, al[mt], bh[g][h2], bh[g][h2 + 2]);
                    }
        }
        __syncthreads();
    }

    // ---- epilogue: fragment layout m16n8: (row=lane>>2 [+8], col=2*(lane&3) [+1]) ----
    #pragma unroll
    for (int mt = 0; mt < 2; mt++) {
        #pragma unroll
        for (int f = 0; f < 8; f++) {
            const int colg = n0 + wn * 64 + f * 8 + (lane & 3) * 2;   // even
            #pragma unroll
            for (int half = 0; half < 2; half++) {
                const int m = m0 + wm * 32 + mt * 16 + (lane >> 2) + half * 8;
                const float v0 = acc[mt][f][half * 2 + 0] + bias[colg];
                const float v1 = acc[mt][f][half * 2 + 1] + bias[colg + 1];
                const int bidx = m >> 11;
                const int l = m & (NL - 1);
                if (MODE == 2) {
                    *(float2*)&out[(size_t)m * NE + colg] = make_float2(v0, v1);
                } else if (MODE == 0) {
                    const int h = colg >> 6, d = colg & 63;
                    *(float2*)&out[((((size_t)bidx * NH + h) * NL) + l) * NHD + d] =
                        make_float2(v0, v1);
                } else {  // RoPE
                    const int h = colg >> 6, d = colg & 63;   // even
                    const float fi = (float)(d >> 1);
                    const float invf = exp2f(fi * (-13.287712379549449f / 32.0f));
                    const float ang = (float)l * invf;
                    float sn, cs;
                    sincosf(ang, &sn, &cs);
                    *(float2*)&out[((((size_t)bidx * NH + h) * NL) + l) * NHD + d] =
                        make_float2(v0 * cs - v1 * sn, v1 * cs + v0 * sn);
                }
            }
        }
    }
}

// ---------------------------------------------------------------------------
// Flash attention (fp32 FFMA) — epilogue writes bf16 hi/lo [b,l,h,d]
// ---------------------------------------------------------------------------
__global__ __launch_bounds__(256, 2)
void attn_kernel(const float* __restrict__ q, const float* __restrict__ k,
                 const float* __restrict__ v,
                 __nv_bfloat16* __restrict__ ohi, __nv_bfloat16* __restrict__ olo)
{
    extern __shared__ float smbuf[];
    float (*Qt)[68] = (float(*)[68])(smbuf);
    float (*Kt)[68] = (float(*)[68])(smbuf + 64*68);
    float (*Vs)[68] = (float(*)[68])(smbuf + 2*64*68);
    float (*Ps)[68] = (float(*)[68])(smbuf + 3*64*68);

    const int tid = threadIdx.x;
    const int tx = tid & 15, ty = tid >> 4;
    const int q0 = blockIdx.x * 64;
    const int bh = blockIdx.y;
    const int b = bh >> 4, h = bh & 15;
    const float* qp = q + (size_t)bh * NL * NHD;
    const float* kp = k + (size_t)bh * NL * NHD;
    const float* vp = v + (size_t)bh * NL * NHD;

    for (int e = tid; e < 1024; e += 256) {
        const int r = e >> 4, d4 = (e & 15) * 4;
        float4 val = *(const float4*)&qp[(size_t)(q0 + r)*NHD + d4];
        Qt[d4+0][r] = val.x; Qt[d4+1][r] = val.y; Qt[d4+2][r] = val.z; Qt[d4+3][r] = val.w;
    }

    float m_i[4], l_i[4], oacc[4][4];
    #pragma unroll
    for (int i = 0; i < 4; i++) {
        m_i[i] = -1e30f; l_i[i] = 0.f;
        #pragma unroll
        for (int j = 0; j < 4; j++) oacc[i][j] = 0.f;
    }

    for (int kt = 0; kt < NL; kt += 64) {
        __syncthreads();
        for (int e = tid; e < 1024; e += 256) {
            const int r = e >> 4, d4 = (e & 15) * 4;
            float4 kv = *(const float4*)&kp[(size_t)(kt + r)*NHD + d4];
            Kt[d4+0][r] = kv.x; Kt[d4+1][r] = kv.y; Kt[d4+2][r] = kv.z; Kt[d4+3][r] = kv.w;
            float4 vv = *(const float4*)&vp[(size_t)(kt + r)*NHD + d4];
            *(float4*)&Vs[r][d4] = vv;
        }
        __syncthreads();

        float s[4][4];
        #pragma unroll
        for (int i = 0; i < 4; i++)
            #pragma unroll
            for (int j = 0; j < 4; j++) s[i][j] = 0.f;

        #pragma unroll 16
        for (int d = 0; d < 64; d++) {
            float qa[4], ka[4];
            *(float4*)qa = *(const float4*)&Qt[d][ty*4];
            *(float4*)ka = *(const float4*)&Kt[d][tx*4];
            #pragma unroll
            for (int i = 0; i < 4; i++)
                #pragma unroll
                for (int j = 0; j < 4; j++)
                    s[i][j] = fmaf(qa[i], ka[j], s[i][j]);
        }

        #pragma unroll
        for (int i = 0; i < 4; i++) {
            #pragma unroll
            for (int j = 0; j < 4; j++) s[i][j] *= 0.125f;
            float rmax = fmaxf(fmaxf(s[i][0], s[i][1]), fmaxf(s[i][2], s[i][3]));
            #pragma unroll
            for (int off = 8; off > 0; off >>= 1)
                rmax = fmaxf(rmax, __shfl_xor_sync(0xffffffffu, rmax, off));
            const float mnew = fmaxf(m_i[i], rmax);
            const float corr = __expf(m_i[i] - mnew);
            m_i[i] = mnew;
            float p[4]; float rsum = 0.f;
            #pragma unroll
            for (int j = 0; j < 4; j++) { p[j] = __expf(s[i][j] - mnew); rsum += p[j]; }
            #pragma unroll
            for (int off = 8; off > 0; off >>= 1)
                rsum += __shfl_xor_sync(0xffffffffu, rsum, off);
            l_i[i] = l_i[i]*corr + rsum;
            #pragma unroll
            for (int j = 0; j < 4; j++) oacc[i][j] *= corr;
            *(float4*)&Ps[ty*4 + i][tx*4] = make_float4(p[0], p[1], p[2], p[3]);
        }
        __syncthreads();

        #pragma unroll 8
        for (int kk = 0; kk < 64; kk++) {
            float4 vv = *(const float4*)&Vs[kk][tx*4];
            #pragma unroll
            for (int i = 0; i < 4; i++) {
                const float pp = Ps[ty*4 + i][kk];
                oacc[i][0] = fmaf(pp, vv.x, oacc[i][0]);
                oacc[i][1] = fmaf(pp, vv.y, oacc[i][1]);
                oacc[i][2] = fmaf(pp, vv.z, oacc[i][2]);
                oacc[i][3] = fmaf(pp, vv.w, oacc[i][3]);
            }
        }
    }

    #pragma unroll
    for (int i = 0; i < 4; i++) {
        const int l = q0 + ty*4 + i;
        const float inv = 1.f / l_i[i];
        const size_t base = (((size_t)b*NL + l)*NH + h)*NHD + tx*4;
        #pragma unroll
        for (int j = 0; j < 4; j++) {
            const float ov = oacc[i][j] * inv;
            __nv_bfloat16 hh = __float2bfloat16(ov);
            ohi[base + j] = hh;
            olo[base + j] = __float2bfloat16(ov - __bfloat162float(hh));
        }
    }
}

// ---------------------------------------------------------------------------
extern "C" void kernel_launch(void* const* d_in, const int* in_sizes, int n_in,
                              void* d_out, int out_size)
{
    (void)in_sizes; (void)n_in; (void)out_size;
    const float* x  = (const float*)d_in[0];
    const float* Wq = (const float*)d_in[1];
    const float* bq = (const float*)d_in[2];
    const float* Wk = (const float*)d_in[3];
    const float* bk = (const float*)d_in[4];
    const float* Wv = (const float*)d_in[5];
    const float* bv = (const float*)d_in[6];
    const float* Wo = (const float*)d_in[7];
    const float* bo = (const float*)d_in[8];

    float *qb, *kb, *vb;
    __nv_bfloat16 *xhi, *xlo, *whi, *wlo, *ahi, *alo;
    cudaGetSymbolAddress((void**)&qb,  g_q);
    cudaGetSymbolAddress((void**)&kb,  g_k);
    cudaGetSymbolAddress((void**)&vb,  g_v);
    cudaGetSymbolAddress((void**)&xhi, g_xhi);
    cudaGetSymbolAddress((void**)&xlo, g_xlo);
    cudaGetSymbolAddress((void**)&whi, g_whi);
    cudaGetSymbolAddress((void**)&wlo, g_wlo);
    cudaGetSymbolAddress((void**)&ahi, g_ahi);
    cudaGetSymbolAddress((void**)&alo, g_alo);

    const int NW = NE * NE;
    split_kernel<<<(NM*NE + 255)/256, 256>>>(x,  xhi, xlo, NM*NE);
    split_kernel<<<(NW + 255)/256, 256>>>(Wq, whi + 0*NW, wlo + 0*NW, NW);
    split_kernel<<<(NW + 255)/256, 256>>>(Wk, whi + 1*NW, wlo + 1*NW, NW);
    split_kernel<<<(NW + 255)/256, 256>>>(Wv, whi + 2*NW, wlo + 2*NW, NW);
    split_kernel<<<(NW + 255)/256, 256>>>(Wo, whi + 3*NW, wlo + 3*NW, NW);

    const int gsmem = 4 * 32768;   // 128 KB
    cudaFuncSetAttribute(gemm_mma<0>, cudaFuncAttributeMaxDynamicSharedMemorySize, gsmem);
    cudaFuncSetAttribute(gemm_mma<1>, cudaFuncAttributeMaxDynamicSharedMemorySize, gsmem);
    cudaFuncSetAttribute(gemm_mma<2>, cudaFuncAttributeMaxDynamicSharedMemorySize, gsmem);

    dim3 gg(NE/128, NM/128);   // (8, 32)
    gemm_mma<1><<<gg, 256, gsmem>>>(xhi, xlo, whi + 0*NW, wlo + 0*NW, bq, qb);
    gemm_mma<1><<<gg, 256, gsmem>>>(xhi, xlo, whi + 1*NW, wlo + 1*NW, bk, kb);
    gemm_mma<0><<<gg, 256, gsmem>>>(xhi, xlo, whi + 2*NW, wlo + 2*NW, bv, vb);

    const int asmem = 4 * 64 * 68 * (int)sizeof(float);   // 69632 B
    cudaFuncSetAttribute(attn_kernel, cudaFuncAttributeMaxDynamicSharedMemorySize, asmem);
    attn_kernel<<<dim3(NL/64, NB*NH), 256, asmem>>>(qb, kb, vb, ahi, alo);

    gemm_mma<2><<<gg, 256, gsmem>>>(ahi, alo, whi + 3*NW, wlo + 3*NW, bo, (float*)d_out);
}

// round 5
// speedup vs baseline: 1.7363x; 1.2526x over previous
#include <cuda_runtime.h>
#include <cuda_bf16.h>
#include <math.h>
#include <stdint.h>

#define NB 2
#define NL 2048
#define NE 1024
#define NH 16
#define NHD 64
#define NM (NB*NL)   /* 4096 rows */

// ---------------- scratch (__device__ globals; no allocation) ----------------
__device__ __nv_bfloat16 g_xhi[NM*NE];
__device__ __nv_bfloat16 g_xlo[NM*NE];
__device__ __nv_bfloat16 g_whi[4*NE*NE];
__device__ __nv_bfloat16 g_wlo[4*NE*NE];
__device__ __nv_bfloat16 g_ahi[NM*NE];
__device__ __nv_bfloat16 g_alo[NM*NE];
__device__ __nv_bfloat16 g_qhi[NB*NH*NL*NHD];
__device__ __nv_bfloat16 g_qlo[NB*NH*NL*NHD];
__device__ __nv_bfloat16 g_khi[NB*NH*NL*NHD];
__device__ __nv_bfloat16 g_klo[NB*NH*NL*NHD];
__device__ __nv_bfloat16 g_vhi[NB*NH*NL*NHD];
__device__ __nv_bfloat16 g_vlo[NB*NH*NL*NHD];

// ---------------- PTX helpers (sm_80-level only) ----------------
__device__ __forceinline__ uint32_t smem_u32(const void* p) {
    uint32_t a;
    asm("{ .reg .u64 t; cvta.to.shared.u64 t, %1; cvt.u32.u64 %0, t; }" : "=r"(a) : "l"(p));
    return a;
}
__device__ __forceinline__ void cp16(uint32_t s, const void* g) {
    asm volatile("cp.async.cg.shared.global [%0], [%1], 16;" :: "r"(s), "l"(g));
}
__device__ __forceinline__ void cp_commit() { asm volatile("cp.async.commit_group;" ::: "memory"); }
__device__ __forceinline__ void cp_wait2()  { asm volatile("cp.async.wait_group 2;" ::: "memory"); }
__device__ __forceinline__ void cp_wait1()  { asm volatile("cp.async.wait_group 1;" ::: "memory"); }

__device__ __forceinline__ void ldsm4(uint32_t* r, uint32_t addr) {
    asm volatile("ldmatrix.sync.aligned.m8n8.x4.shared.b16 {%0,%1,%2,%3}, [%4];"
                 : "=r"(r[0]), "=r"(r[1]), "=r"(r[2]), "=r"(r[3]) : "r"(addr));
}
__device__ __forceinline__ void ldsm4t(uint32_t* r, uint32_t addr) {
    asm volatile("ldmatrix.sync.aligned.m8n8.x4.trans.shared.b16 {%0,%1,%2,%3}, [%4];"
                 : "=r"(r[0]), "=r"(r[1]), "=r"(r[2]), "=r"(r[3]) : "r"(addr));
}
__device__ __forceinline__ void mma16816(float* d, const uint32_t* a, uint32_t b0, uint32_t b1) {
    asm volatile("mma.sync.aligned.m16n8k16.row.col.f32.bf16.bf16.f32 "
                 "{%0,%1,%2,%3}, {%4,%5,%6,%7}, {%8,%9}, {%0,%1,%2,%3};"
                 : "+f"(d[0]), "+f"(d[1]), "+f"(d[2]), "+f"(d[3])
                 : "r"(a[0]), "r"(a[1]), "r"(a[2]), "r"(a[3]), "r"(b0), "r"(b1));
}

// split (x,y) into packed bf16x2 hi and lo words
__device__ __forceinline__ void split2(float x, float y, uint32_t& hp, uint32_t& lp) {
    __nv_bfloat16 hx = __float2bfloat16(x), hy = __float2bfloat16(y);
    float rx = x - __bfloat162float(hx), ry = y - __bfloat162float(hy);
    __nv_bfloat16 lx = __float2bfloat16(rx), ly = __float2bfloat16(ry);
    hp = (uint32_t)__bfloat16_as_ushort(hx) | ((uint32_t)__bfloat16_as_ushort(hy) << 16);
    lp = (uint32_t)__bfloat16_as_ushort(lx) | ((uint32_t)__bfloat16_as_ushort(ly) << 16);
}

// ---------------- split fp32 -> bf16 hi/lo ----------------
__global__ void split_kernel(const float* __restrict__ in,
                             __nv_bfloat16* __restrict__ hi,
                             __nv_bfloat16* __restrict__ lo, int n)
{
    int i = blockIdx.x * blockDim.x + threadIdx.x;
    if (i < n) {
        float v = in[i];
        __nv_bfloat16 h = __float2bfloat16(v);
        hi[i] = h;
        lo[i] = __float2bfloat16(v - __bfloat162float(h));
    }
}

// ---------------------------------------------------------------------------
// HMMA GEMM: D[m,n] = sum_k A[m,k]*B[n,k] + bias[n]; bf16 split, 3 products.
// MODE 0: v  -> bf16 hi/lo [b,h,l,d]
// MODE 1: q  -> RoPE, *0.125, bf16 hi/lo [b,h,l,d]
// MODE 3: k  -> RoPE, bf16 hi/lo [b,h,l,d]
// MODE 2: fp32 [m,n] + bias (final output)
// ---------------------------------------------------------------------------
template<int MODE>
__global__ __launch_bounds__(256, 1)
void gemm_mma(const __nv_bfloat16* __restrict__ Ahi, const __nv_bfloat16* __restrict__ Alo,
              const __nv_bfloat16* __restrict__ Bhi, const __nv_bfloat16* __restrict__ Blo,
              const float* __restrict__ bias, void* __restrict__ out_hi,
              void* __restrict__ out_lo)
{
    extern __shared__ char smraw[];
    const uint32_t sm0 = smem_u32(smraw);

    const int tid = threadIdx.x;
    const int lane = tid & 31, w = tid >> 5;
    const int wm = w & 3, wn = w >> 2;
    const int m0 = blockIdx.y * 128, n0 = blockIdx.x * 128;

    auto load_stage = [&](int stage, int buf) {
        const uint32_t base = sm0 + (uint32_t)buf * 32768u;
        const int kc = stage * 32;
        #pragma unroll
        for (int i = tid; i < 512; i += 256) {
            const int row = i >> 2, c = i & 3;
            const int cs = c ^ ((row >> 1) & 3);
            const uint32_t off = (uint32_t)(row * 64 + cs * 16);
            const size_t ga = (size_t)(m0 + row) * NE + kc + c * 8;
            const size_t gb = (size_t)(n0 + row) * NE + kc + c * 8;
            cp16(base +          off, Ahi + ga);
            cp16(base +  8192u + off, Alo + ga);
            cp16(base + 16384u + off, Bhi + gb);
            cp16(base + 24576u + off, Blo + gb);
        }
        cp_commit();
    };

    load_stage(0, 0); load_stage(1, 1); load_stage(2, 2);

    float acc[2][8][4];
    #pragma unroll
    for (int a = 0; a < 2; a++)
        #pragma unroll
        for (int b = 0; b < 8; b++)
            #pragma unroll
            for (int c = 0; c < 4; c++) acc[a][b][c] = 0.f;

    const int NS = NE / 32;
    for (int t = 0; t < NS; t++) {
        cp_wait2();
        __syncthreads();
        if (t + 3 < NS) load_stage(t + 3, (t + 3) & 3); else cp_commit();

        const uint32_t base = sm0 + (uint32_t)(t & 3) * 32768u;
        #pragma unroll
        for (int s = 0; s < 2; s++) {
            const int chunk = 2 * s + (lane >> 4);
            uint32_t ah[2][4], al[2][4];
            #pragma unroll
            for (int mt = 0; mt < 2; mt++) {
                const int row = wm * 32 + mt * 16 + (lane & 15);
                const int cs = chunk ^ ((row >> 1) & 3);
                const uint32_t a = base + (uint32_t)(row * 64 + cs * 16);
                ldsm4(ah[mt], a);
                ldsm4(al[mt], a + 8192u);
            }
            uint32_t bh[4][4], bl[4][4];
            #pragma unroll
            for (int g = 0; g < 4; g++) {
                const int row = wn * 64 + g * 16 + (lane & 15);
                const int cs = chunk ^ ((row >> 1) & 3);
                const uint32_t a = base + 16384u + (uint32_t)(row * 64 + cs * 16);
                ldsm4(bh[g], a);
                ldsm4(bl[g], a + 8192u);
            }
            #pragma unroll
            for (int mt = 0; mt < 2; mt++)
                #pragma unroll
                for (int g = 0; g < 4; g++)
                    #pragma unroll
                    for (int h2 = 0; h2 < 2; h2++) {
                        float* d = acc[mt][g * 2 + h2];
                        mma16816(d, ah[mt], bh[g][h2], bh[g][h2 + 2]);
                        mma16816(d, ah[mt], bl[g][h2], bl[g][h2 + 2]);
                        mma16816(d, al[mt], bh[g][h2], bh[g][h2 + 2]);
                    }
        }
        __syncthreads();
    }

    #pragma unroll
    for (int mt = 0; mt < 2; mt++) {
        #pragma unroll
        for (int f = 0; f < 8; f++) {
            const int colg = n0 + wn * 64 + f * 8 + (lane & 3) * 2;   // even
            #pragma unroll
            for (int half = 0; half < 2; half++) {
                const int m = m0 + wm * 32 + mt * 16 + (lane >> 2) + half * 8;
                float v0 = acc[mt][f][half * 2 + 0] + bias[colg];
                float v1 = acc[mt][f][half * 2 + 1] + bias[colg + 1];
                const int bidx = m >> 11;
                const int l = m & (NL - 1);
                if (MODE == 2) {
                    float* o = (float*)out_hi;
                    *(float2*)&o[(size_t)m * NE + colg] = make_float2(v0, v1);
                } else {
                    const int h = colg >> 6, d = colg & 63;   // even d
                    if (MODE != 0) {   // RoPE
                        const float fi = (float)(d >> 1);
                        const float invf = exp2f(fi * (-13.287712379549449f / 32.0f));
                        const float ang = (float)l * invf;
                        float sn, cs;
                        sincosf(ang, &sn, &cs);
                        const float r0 = v0 * cs - v1 * sn;
                        const float r1 = v1 * cs + v0 * sn;
                        v0 = r0; v1 = r1;
                        if (MODE == 1) { v0 *= 0.125f; v1 *= 0.125f; }
                    }
                    uint32_t hp, lp;
                    split2(v0, v1, hp, lp);
                    const size_t idx = ((((size_t)bidx * NH + h) * NL) + l) * NHD + d;
                    *(uint32_t*)((__nv_bfloat16*)out_hi + idx) = hp;
                    *(uint32_t*)((__nv_bfloat16*)out_lo + idx) = lp;
                }
            }
        }
    }
}

// ---------------------------------------------------------------------------
// Tensor-core flash attention. CTA: 128 q-rows of one (b,h); 8 warps x 16 rows.
// Key tiles of 64, double-buffered cp.async. All matmuls bf16-split HMMA.
// Q scaled by 1/8 upstream. Writes output bf16 hi/lo at [b, l, h, d].
// smem: Qhi 16K | Qlo 16K | 2 stages x {Khi 8K | Klo 8K | Vhi 8K | Vlo 8K}.
// ---------------------------------------------------------------------------
__global__ __launch_bounds__(256, 1)
void attn_mma(const __nv_bfloat16* __restrict__ qhi, const __nv_bfloat16* __restrict__ qlo,
              const __nv_bfloat16* __restrict__ khi, const __nv_bfloat16* __restrict__ klo,
              const __nv_bfloat16* __restrict__ vhi, const __nv_bfloat16* __restrict__ vlo,
              __nv_bfloat16* __restrict__ ohi, __nv_bfloat16* __restrict__ olo)
{
    extern __shared__ char smraw[];
    const uint32_t sq  = smem_u32(smraw);
    const uint32_t skv = sq + 32768u;

    const int tid = threadIdx.x;
    const int lane = tid & 31, w = tid >> 5;
    const int q0 = blockIdx.x * 128;
    const int bh = blockIdx.y;
    const int b = bh >> 4, h = bh & 15;
    const size_t kvbase_g = (size_t)bh * NL * NHD;

    // ---- Q tiles (hi/lo), swizzled 128B rows ----
    #pragma unroll
    for (int i = tid; i < 1024; i += 256) {
        const int row = i >> 3, c = i & 7;
        const uint32_t off = (uint32_t)(row * 128 + ((c ^ (row & 7)) * 16));
        const size_t g = kvbase_g + (size_t)(q0 + row) * NHD + c * 8;
        cp16(sq + off, qhi + g);
        cp16(sq + 16384u + off, qlo + g);
    }

    auto load_kv = [&](int kt, int buf) {
        const uint32_t base = skv + (uint32_t)buf * 32768u;
        #pragma unroll
        for (int i = tid; i < 512; i += 256) {
            const int row = i >> 3, c = i & 7;
            const uint32_t off = (uint32_t)(row * 128 + ((c ^ (row & 7)) * 16));
            const size_t g = kvbase_g + (size_t)(kt * 64 + row) * NHD + c * 8;
            cp16(base +          off, khi + g);
            cp16(base +  8192u + off, klo + g);
            cp16(base + 16384u + off, vhi + g);
            cp16(base + 24576u + off, vlo + g);
        }
    };

    load_kv(0, 0); cp_commit();     // group: Q + stage0
    load_kv(1, 1); cp_commit();     // group: stage1

    float o[8][4];
    #pragma unroll
    for (int f = 0; f < 8; f++)
        #pragma unroll
        for (int j = 0; j < 4; j++) o[f][j] = 0.f;
    float m0r = -1e30f, m1r = -1e30f, l0r = 0.f, l1r = 0.f;

    const int NT = NL / 64;   // 32
    for (int t = 0; t < NT; t++) {
        cp_wait1();
        __syncthreads();
        const uint32_t base = skv + (uint32_t)(t & 1) * 32768u;

        // ---- S = Q K^T ----
        float s[8][4];
        #pragma unroll
        for (int f = 0; f < 8; f++)
            #pragma unroll
            for (int j = 0; j < 4; j++) s[f][j] = 0.f;

        #pragma unroll
        for (int kc = 0; kc < 4; kc++) {
            uint32_t ah[4], al[4];
            {
                const int row = w * 16 + (lane & 15);
                const int chunk = 2 * kc + (lane >> 4);
                const uint32_t a = sq + (uint32_t)(row * 128 + ((chunk ^ (row & 7)) * 16));
                ldsm4(ah, a);
                ldsm4(al, a + 16384u);
            }
            #pragma unroll
            for (int g = 0; g < 4; g++) {
                uint32_t kh[4], kl[4];
                const int row = g * 16 + (lane & 15);
                const int chunk = 2 * kc + (lane >> 4);
                const uint32_t a = base + (uint32_t)(row * 128 + ((chunk ^ (row & 7)) * 16));
                ldsm4(kh, a);
                ldsm4(kl, a + 8192u);
                #pragma unroll
                for (int h2 = 0; h2 < 2; h2++) {
                    float* d = s[2 * g + h2];
                    mma16816(d, ah, kh[h2], kh[h2 + 2]);
                    mma16816(d, ah, kl[h2], kl[h2 + 2]);
                    mma16816(d, al, kh[h2], kh[h2 + 2]);
                }
            }
        }

        // ---- online softmax (rows r0 = lane>>2, r1 = r0+8 of this warp) ----
        float mx0 = -1e30f, mx1 = -1e30f;
        #pragma unroll
        for (int f = 0; f < 8; f++) {
            mx0 = fmaxf(mx0, fmaxf(s[f][0], s[f][1]));
            mx1 = fmaxf(mx1, fmaxf(s[f][2], s[f][3]));
        }
        #pragma unroll
        for (int off = 1; off <= 2; off <<= 1) {
            mx0 = fmaxf(mx0, __shfl_xor_sync(0xffffffffu, mx0, off));
            mx1 = fmaxf(mx1, __shfl_xor_sync(0xffffffffu, mx1, off));
        }
        const float mn0 = fmaxf(m0r, mx0), mn1 = fmaxf(m1r, mx1);
        const float c0 = __expf(m0r - mn0), c1 = __expf(m1r - mn1);
        m0r = mn0; m1r = mn1;

        float su0 = 0.f, su1 = 0.f;
        #pragma unroll
        for (int f = 0; f < 8; f++) {
            s[f][0] = __expf(s[f][0] - mn0); su0 += s[f][0];
            s[f][1] = __expf(s[f][1] - mn0); su0 += s[f][1];
            s[f][2] = __expf(s[f][2] - mn1); su1 += s[f][2];
            s[f][3] = __expf(s[f][3] - mn1); su1 += s[f][3];
        }
        #pragma unroll
        for (int off = 1; off <= 2; off <<= 1) {
            su0 += __shfl_xor_sync(0xffffffffu, su0, off);
            su1 += __shfl_xor_sync(0xffffffffu, su1, off);
        }
        l0r = l0r * c0 + su0;
        l1r = l1r * c1 + su1;
        #pragma unroll
        for (int f = 0; f < 8; f++) {
            o[f][0] *= c0; o[f][1] *= c0;
            o[f][2] *= c1; o[f][3] *= c1;
        }

        // ---- O += P V  (P from accum frags, repacked bf16 hi/lo) ----
        #pragma unroll
        for (int kc = 0; kc < 4; kc++) {
            uint32_t ph[4], pl[4];
            split2(s[2*kc][0],   s[2*kc][1],   ph[0], pl[0]);
            split2(s[2*kc][2],   s[2*kc][3],   ph[1], pl[1]);
            split2(s[2*kc+1][0], s[2*kc+1][1], ph[2], pl[2]);
            split2(s[2*kc+1][2], s[2*kc+1][3], ph[3], pl[3]);
            #pragma unroll
            for (int g = 0; g < 4; g++) {
                uint32_t vh[4], vl[4];
                const int row = kc * 16 + (lane & 15);
                const int chunk = 2 * g + (lane >> 4);
                const uint32_t a = base + 16384u + (uint32_t)(row * 128 + ((chunk ^ (row & 7)) * 16));
                ldsm4t(vh, a);
                ldsm4t(vl, a + 8192u);
                mma16816(o[2*g],   ph, vh[0], vh[1]);
                mma16816(o[2*g],   ph, vl[0], vl[1]);
                mma16816(o[2*g],   pl, vh[0], vh[1]);
                mma16816(o[2*g+1], ph, vh[2], vh[3]);
                mma16816(o[2*g+1], ph, vl[2], vl[3]);
                mma16816(o[2*g+1], pl, vh[2], vh[3]);
            }
        }

        __syncthreads();
        if (t + 2 < NT) load_kv(t + 2, t & 1);
        cp_commit();
    }

    // ---- epilogue: normalize, split, write [b, l, h, d] ----
    const float inv0 = 1.f / l0r, inv1 = 1.f / l1r;
    const int lr0 = q0 + w * 16 + (lane >> 2);
    #pragma unroll
    for (int f = 0; f < 8; f++) {
        const int d = f * 8 + (lane & 3) * 2;
        uint32_t hp, lp;
        split2(o[f][0] * inv0, o[f][1] * inv0, hp, lp);
        size_t idx = (((size_t)b * NL + lr0) * NH + h) * NHD + d;
        *(uint32_t*)(ohi + idx) = hp;
        *(uint32_t*)(olo + idx) = lp;
        split2(o[f][2] * inv1, o[f][3] * inv1, hp, lp);
        idx = (((size_t)b * NL + lr0 + 8) * NH + h) * NHD + d;
        *(uint32_t*)(ohi + idx) = hp;
        *(uint32_t*)(olo + idx) = lp;
    }
}

// ---------------------------------------------------------------------------
extern "C" void kernel_launch(void* const* d_in, const int* in_sizes, int n_in,
                              void* d_out, int out_size)
{
    (void)in_sizes; (void)n_in; (void)out_size;
    const float* x  = (const float*)d_in[0];
    const float* Wq = (const float*)d_in[1];
    const float* bq = (const float*)d_in[2];
    const float* Wk = (const float*)d_in[3];
    const float* bk = (const float*)d_in[4];
    const float* Wv = (const float*)d_in[5];
    const float* bv = (const float*)d_in[6];
    const float* Wo = (const float*)d_in[7];
    const float* bo = (const float*)d_in[8];

    __nv_bfloat16 *xhi, *xlo, *whi, *wlo, *ahi, *alo;
    __nv_bfloat16 *qhi, *qlo, *khi, *klo, *vhi, *vlo;
    cudaGetSymbolAddress((void**)&xhi, g_xhi);
    cudaGetSymbolAddress((void**)&xlo, g_xlo);
    cudaGetSymbolAddress((void**)&whi, g_whi);
    cudaGetSymbolAddress((void**)&wlo, g_wlo);
    cudaGetSymbolAddress((void**)&ahi, g_ahi);
    cudaGetSymbolAddress((void**)&alo, g_alo);
    cudaGetSymbolAddress((void**)&qhi, g_qhi);
    cudaGetSymbolAddress((void**)&qlo, g_qlo);
    cudaGetSymbolAddress((void**)&khi, g_khi);
    cudaGetSymbolAddress((void**)&klo, g_klo);
    cudaGetSymbolAddress((void**)&vhi, g_vhi);
    cudaGetSymbolAddress((void**)&vlo, g_vlo);

    const int NW = NE * NE;
    split_kernel<<<(NM*NE + 255)/256, 256>>>(x,  xhi, xlo, NM*NE);
    split_kernel<<<(NW + 255)/256, 256>>>(Wq, whi + 0*NW, wlo + 0*NW, NW);
    split_kernel<<<(NW + 255)/256, 256>>>(Wk, whi + 1*NW, wlo + 1*NW, NW);
    split_kernel<<<(NW + 255)/256, 256>>>(Wv, whi + 2*NW, wlo + 2*NW, NW);
    split_kernel<<<(NW + 255)/256, 256>>>(Wo, whi + 3*NW, wlo + 3*NW, NW);

    const int gsmem = 4 * 32768;   // 128 KB
    cudaFuncSetAttribute(gemm_mma<0>, cudaFuncAttributeMaxDynamicSharedMemorySize, gsmem);
    cudaFuncSetAttribute(gemm_mma<1>, cudaFuncAttributeMaxDynamicSharedMemorySize, gsmem);
    cudaFuncSetAttribute(gemm_mma<2>, cudaFuncAttributeMaxDynamicSharedMemorySize, gsmem);
    cudaFuncSetAttribute(gemm_mma<3>, cudaFuncAttributeMaxDynamicSharedMemorySize, gsmem);

    dim3 gg(NE/128, NM/128);   // (8, 32)
    gemm_mma<1><<<gg, 256, gsmem>>>(xhi, xlo, whi + 0*NW, wlo + 0*NW, bq, qhi, qlo);
    gemm_mma<3><<<gg, 256, gsmem>>>(xhi, xlo, whi + 1*NW, wlo + 1*NW, bk, khi, klo);
    gemm_mma<0><<<gg, 256, gsmem>>>(xhi, xlo, whi + 2*NW, wlo + 2*NW, bv, vhi, vlo);

    const int asmem = 32768 + 2 * 32768;   // 96 KB
    cudaFuncSetAttribute(attn_mma, cudaFuncAttributeMaxDynamicSharedMemorySize, asmem);
    attn_mma<<<dim3(NL/128, NB*NH), 256, asmem>>>(qhi, qlo, khi, klo, vhi, vlo, ahi, alo);

    gemm_mma<2><<<gg, 256, gsmem>>>(ahi, alo, whi + 3*NW, wlo + 3*NW, bo, d_out, nullptr);
}

// round 6
// speedup vs baseline: 2.6716x; 1.5386x over previous
#include <cuda_runtime.h>
#include <cuda_bf16.h>
#include <math.h>
#include <stdint.h>

#define NB 2
#define NL 2048
#define NE 1024
#define NH 16
#define NHD 64
#define NM (NB*NL)   /* 4096 rows */
#define NW (NE*NE)

// ---------------- scratch (__device__ globals; no allocation) ----------------
__device__ __nv_bfloat16 g_xhi[NM*NE];
__device__ __nv_bfloat16 g_xlo[NM*NE];
__device__ __nv_bfloat16 g_whi[4*NE*NE];
__device__ __nv_bfloat16 g_wlo[4*NE*NE];
__device__ __nv_bfloat16 g_ahi[NM*NE];
__device__ __nv_bfloat16 g_alo[NM*NE];
__device__ __nv_bfloat16 g_qhi[NB*NH*NL*NHD];
__device__ __nv_bfloat16 g_qlo[NB*NH*NL*NHD];
__device__ __nv_bfloat16 g_khi[NB*NH*NL*NHD];
__device__ __nv_bfloat16 g_klo[NB*NH*NL*NHD];
__device__ __nv_bfloat16 g_vhi[NB*NH*NL*NHD];
__device__ __nv_bfloat16 g_vlo[NB*NH*NL*NHD];
__device__ float g_ctab[NL*32];
__device__ float g_stab[NL*32];

// ---------------- PTX helpers (sm_80-level only) ----------------
__device__ __forceinline__ uint32_t smem_u32(const void* p) {
    uint32_t a;
    asm("{ .reg .u64 t; cvta.to.shared.u64 t, %1; cvt.u32.u64 %0, t; }" : "=r"(a) : "l"(p));
    return a;
}
__device__ __forceinline__ void cp16(uint32_t s, const void* g) {
    asm volatile("cp.async.cg.shared.global [%0], [%1], 16;" :: "r"(s), "l"(g));
}
__device__ __forceinline__ void cp_commit() { asm volatile("cp.async.commit_group;" ::: "memory"); }
__device__ __forceinline__ void cp_wait2()  { asm volatile("cp.async.wait_group 2;" ::: "memory"); }
__device__ __forceinline__ void cp_wait1()  { asm volatile("cp.async.wait_group 1;" ::: "memory"); }

__device__ __forceinline__ void ldsm4(uint32_t* r, uint32_t addr) {
    asm volatile("ldmatrix.sync.aligned.m8n8.x4.shared.b16 {%0,%1,%2,%3}, [%4];"
                 : "=r"(r[0]), "=r"(r[1]), "=r"(r[2]), "=r"(r[3]) : "r"(addr));
}
__device__ __forceinline__ void ldsm4t(uint32_t* r, uint32_t addr) {
    asm volatile("ldmatrix.sync.aligned.m8n8.x4.trans.shared.b16 {%0,%1,%2,%3}, [%4];"
                 : "=r"(r[0]), "=r"(r[1]), "=r"(r[2]), "=r"(r[3]) : "r"(addr));
}
__device__ __forceinline__ void mma16816(float* d, const uint32_t* a, uint32_t b0, uint32_t b1) {
    asm volatile("mma.sync.aligned.m16n8k16.row.col.f32.bf16.bf16.f32 "
                 "{%0,%1,%2,%3}, {%4,%5,%6,%7}, {%8,%9}, {%0,%1,%2,%3};"
                 : "+f"(d[0]), "+f"(d[1]), "+f"(d[2]), "+f"(d[3])
                 : "r"(a[0]), "r"(a[1]), "r"(a[2]), "r"(a[3]), "r"(b0), "r"(b1));
}

__device__ __forceinline__ void split2(float x, float y, uint32_t& hp, uint32_t& lp) {
    __nv_bfloat16 hx = __float2bfloat16(x), hy = __float2bfloat16(y);
    float rx = x - __bfloat162float(hx), ry = y - __bfloat162float(hy);
    __nv_bfloat16 lx = __float2bfloat16(rx), ly = __float2bfloat16(ry);
    hp = (uint32_t)__bfloat16_as_ushort(hx) | ((uint32_t)__bfloat16_as_ushort(hy) << 16);
    lp = (uint32_t)__bfloat16_as_ushort(lx) | ((uint32_t)__bfloat16_as_ushort(ly) << 16);
}

// ---------------- RoPE cos/sin table: [l][d2], d2 = d/2 in 0..31 ----------------
__global__ void rope_table_kernel() {
    const int i = blockIdx.x * 256 + threadIdx.x;   // < 65536
    const int l = i >> 5, d2 = i & 31;
    const float invf = exp2f((float)d2 * (-13.287712379549449f / 32.0f));
    float sn, cs;
    sincosf((float)l * invf, &sn, &cs);
    g_ctab[i] = cs;
    g_stab[i] = sn;
}

// ---------------- vectorized split: 8 elements / thread ----------------
__global__ void split8_kernel(const float4* __restrict__ in,
                              uint4* __restrict__ hi, uint4* __restrict__ lo, int n8)
{
    const int i = blockIdx.x * blockDim.x + threadIdx.x;
    if (i >= n8) return;
    const float4 a = in[2*i], b = in[2*i + 1];
    uint32_t hw[4], lw[4];
    split2(a.x, a.y, hw[0], lw[0]);
    split2(a.z, a.w, hw[1], lw[1]);
    split2(b.x, b.y, hw[2], lw[2]);
    split2(b.z, b.w, hw[3], lw[3]);
    hi[i] = make_uint4(hw[0], hw[1], hw[2], hw[3]);
    lo[i] = make_uint4(lw[0], lw[1], lw[2], lw[3]);
}

// ---------------------------------------------------------------------------
// Shared GEMM mainloop (CTA 128x128, BK=32, 8 warps 4x2, 4-stage cp.async).
// Produces acc[2][8][4] per thread.
// ---------------------------------------------------------------------------
struct GemmCtx {
    float acc[2][8][4];
};

__device__ __forceinline__ void gemm_mainloop(
    const __nv_bfloat16* __restrict__ Ahi, const __nv_bfloat16* __restrict__ Alo,
    const __nv_bfloat16* __restrict__ Bhi, const __nv_bfloat16* __restrict__ Blo,
    int m0, int n0, uint32_t sm0, GemmCtx& cx)
{
    const int tid = threadIdx.x;
    const int lane = tid & 31, w = tid >> 5;
    const int wm = w & 3, wn = w >> 2;

    auto load_stage = [&](int stage, int buf) {
        const uint32_t base = sm0 + (uint32_t)buf * 32768u;
        const int kc = stage * 32;
        #pragma unroll
        for (int i = tid; i < 512; i += 256) {
            const int row = i >> 2, c = i & 3;
            const int cs = c ^ ((row >> 1) & 3);
            const uint32_t off = (uint32_t)(row * 64 + cs * 16);
            const size_t ga = (size_t)(m0 + row) * NE + kc + c * 8;
            const size_t gb = (size_t)(n0 + row) * NE + kc + c * 8;
            cp16(base +          off, Ahi + ga);
            cp16(base +  8192u + off, Alo + ga);
            cp16(base + 16384u + off, Bhi + gb);
            cp16(base + 24576u + off, Blo + gb);
        }
        cp_commit();
    };

    load_stage(0, 0); load_stage(1, 1); load_stage(2, 2);

    #pragma unroll
    for (int a = 0; a < 2; a++)
        #pragma unroll
        for (int b = 0; b < 8; b++)
            #pragma unroll
            for (int c = 0; c < 4; c++) cx.acc[a][b][c] = 0.f;

    const int NS = NE / 32;
    for (int t = 0; t < NS; t++) {
        cp_wait2();
        __syncthreads();
        if (t + 3 < NS) load_stage(t + 3, (t + 3) & 3); else cp_commit();

        const uint32_t base = sm0 + (uint32_t)(t & 3) * 32768u;
        #pragma unroll
        for (int s = 0; s < 2; s++) {
            const int chunk = 2 * s + (lane >> 4);
            uint32_t ah[2][4], al[2][4];
            #pragma unroll
            for (int mt = 0; mt < 2; mt++) {
                const int row = wm * 32 + mt * 16 + (lane & 15);
                const int cs = chunk ^ ((row >> 1) & 3);
                const uint32_t a = base + (uint32_t)(row * 64 + cs * 16);
                ldsm4(ah[mt], a);
                ldsm4(al[mt], a + 8192u);
            }
            uint32_t bh[4][4], bl[4][4];
            #pragma unroll
            for (int g = 0; g < 4; g++) {
                const int row = wn * 64 + g * 16 + (lane & 15);
                const int cs = chunk ^ ((row >> 1) & 3);
                const uint32_t a = base + 16384u + (uint32_t)(row * 64 + cs * 16);
                ldsm4(bh[g], a);
                ldsm4(bl[g], a + 8192u);
            }
            #pragma unroll
            for (int mt = 0; mt < 2; mt++)
                #pragma unroll
                for (int g = 0; g < 4; g++)
                    #pragma unroll
                    for (int h2 = 0; h2 < 2; h2++) {
                        float* d = cx.acc[mt][g * 2 + h2];
                        mma16816(d, ah[mt], bh[g][h2], bh[g][h2 + 2]);
                        mma16816(d, ah[mt], bl[g][h2], bl[g][h2 + 2]);
                        mma16816(d, al[mt], bh[g][h2], bh[g][h2 + 2]);
                    }
        }
        __syncthreads();
    }
}

// ---------------------------------------------------------------------------
// Fused QKV projection. grid (8, 32, 3); z: 0=q (RoPE+0.125), 1=k (RoPE), 2=v.
// Writes bf16 hi/lo at [b,h,l,d].
// ---------------------------------------------------------------------------
__global__ __launch_bounds__(256, 1)
void qkv_gemm(const __nv_bfloat16* __restrict__ xhi, const __nv_bfloat16* __restrict__ xlo,
              const __nv_bfloat16* __restrict__ whi, const __nv_bfloat16* __restrict__ wlo,
              const float* __restrict__ bq, const float* __restrict__ bk,
              const float* __restrict__ bv,
              __nv_bfloat16* __restrict__ qhi, __nv_bfloat16* __restrict__ qlo,
              __nv_bfloat16* __restrict__ khi, __nv_bfloat16* __restrict__ klo,
              __nv_bfloat16* __restrict__ vhi, __nv_bfloat16* __restrict__ vlo)
{
    extern __shared__ char smraw[];
    const uint32_t sm0 = smem_u32(smraw);
    const int z = blockIdx.z;
    const int m0 = blockIdx.y * 128, n0 = blockIdx.x * 128;

    const float* bias = (z == 0) ? bq : (z == 1) ? bk : bv;
    __nv_bfloat16* OH = (z == 0) ? qhi : (z == 1) ? khi : vhi;
    __nv_bfloat16* OL = (z == 0) ? qlo : (z == 1) ? klo : vlo;

    GemmCtx cx;
    gemm_mainloop(xhi, xlo, whi + (size_t)z * NW, wlo + (size_t)z * NW, m0, n0, sm0, cx);

    const int lane = threadIdx.x & 31, w = threadIdx.x >> 5;
    const int wm = w & 3, wn = w >> 2;

    #pragma unroll
    for (int mt = 0; mt < 2; mt++) {
        #pragma unroll
        for (int f = 0; f < 8; f++) {
            const int colg = n0 + wn * 64 + f * 8 + (lane & 3) * 2;   // even
            const int h = colg >> 6, d = colg & 63;
            const int d2 = d >> 1;
            #pragma unroll
            for (int half = 0; half < 2; half++) {
                const int m = m0 + wm * 32 + mt * 16 + (lane >> 2) + half * 8;
                float v0 = cx.acc[mt][f][half * 2 + 0] + bias[colg];
                float v1 = cx.acc[mt][f][half * 2 + 1] + bias[colg + 1];
                const int bidx = m >> 11;
                const int l = m & (NL - 1);
                if (z < 2) {
                    const float cs = __ldg(&g_ctab[l * 32 + d2]);
                    const float sn = __ldg(&g_stab[l * 32 + d2]);
                    float r0 = v0 * cs - v1 * sn;
                    float r1 = v1 * cs + v0 * sn;
                    if (z == 0) { r0 *= 0.125f; r1 *= 0.125f; }
                    v0 = r0; v1 = r1;
                }
                uint32_t hp, lp;
                split2(v0, v1, hp, lp);
                const size_t idx = ((((size_t)bidx * NH + h) * NL) + l) * NHD + d;
                *(uint32_t*)(OH + idx) = hp;
                *(uint32_t*)(OL + idx) = lp;
            }
        }
    }
}

// ---------------------------------------------------------------------------
// Output projection: fp32 [m,n] + bias
// ---------------------------------------------------------------------------
__global__ __launch_bounds__(256, 1)
void out_gemm(const __nv_bfloat16* __restrict__ Ahi, const __nv_bfloat16* __restrict__ Alo,
              const __nv_bfloat16* __restrict__ Bhi, const __nv_bfloat16* __restrict__ Blo,
              const float* __restrict__ bias, float* __restrict__ out)
{
    extern __shared__ char smraw[];
    const uint32_t sm0 = smem_u32(smraw);
    const int m0 = blockIdx.y * 128, n0 = blockIdx.x * 128;

    GemmCtx cx;
    gemm_mainloop(Ahi, Alo, Bhi, Blo, m0, n0, sm0, cx);

    const int lane = threadIdx.x & 31, w = threadIdx.x >> 5;
    const int wm = w & 3, wn = w >> 2;

    #pragma unroll
    for (int mt = 0; mt < 2; mt++) {
        #pragma unroll
        for (int f = 0; f < 8; f++) {
            const int colg = n0 + wn * 64 + f * 8 + (lane & 3) * 2;
            #pragma unroll
            for (int half = 0; half < 2; half++) {
                const int m = m0 + wm * 32 + mt * 16 + (lane >> 2) + half * 8;
                const float v0 = cx.acc[mt][f][half * 2 + 0] + bias[colg];
                const float v1 = cx.acc[mt][f][half * 2 + 1] + bias[colg + 1];
                *(float2*)&out[(size_t)m * NE + colg] = make_float2(v0, v1);
            }
        }
    }
}

// ---------------------------------------------------------------------------
// Tensor-core flash attention (same math as R5); target 2 CTAs/SM.
// ---------------------------------------------------------------------------
__global__ __launch_bounds__(256, 2)
void attn_mma(const __nv_bfloat16* __restrict__ qhi, const __nv_bfloat16* __restrict__ qlo,
              const __nv_bfloat16* __restrict__ khi, const __nv_bfloat16* __restrict__ klo,
              const __nv_bfloat16* __restrict__ vhi, const __nv_bfloat16* __restrict__ vlo,
              __nv_bfloat16* __restrict__ ohi, __nv_bfloat16* __restrict__ olo)
{
    extern __shared__ char smraw[];
    const uint32_t sq  = smem_u32(smraw);
    const uint32_t skv = sq + 32768u;

    const int tid = threadIdx.x;
    const int lane = tid & 31, w = tid >> 5;
    const int q0 = blockIdx.x * 128;
    const int bh = blockIdx.y;
    const int b = bh >> 4, h = bh & 15;
    const size_t kvbase_g = (size_t)bh * NL * NHD;

    #pragma unroll
    for (int i = tid; i < 1024; i += 256) {
        const int row = i >> 3, c = i & 7;
        const uint32_t off = (uint32_t)(row * 128 + ((c ^ (row & 7)) * 16));
        const size_t g = kvbase_g + (size_t)(q0 + row) * NHD + c * 8;
        cp16(sq + off, qhi + g);
        cp16(sq + 16384u + off, qlo + g);
    }

    auto load_kv = [&](int kt, int buf) {
        const uint32_t base = skv + (uint32_t)buf * 32768u;
        #pragma unroll
        for (int i = tid; i < 512; i += 256) {
            const int row = i >> 3, c = i & 7;
            const uint32_t off = (uint32_t)(row * 128 + ((c ^ (row & 7)) * 16));
            const size_t g = kvbase_g + (size_t)(kt * 64 + row) * NHD + c * 8;
            cp16(base +          off, khi + g);
            cp16(base +  8192u + off, klo + g);
            cp16(base + 16384u + off, vhi + g);
            cp16(base + 24576u + off, vlo + g);
        }
    };

    load_kv(0, 0); cp_commit();
    load_kv(1, 1); cp_commit();

    float o[8][4];
    #pragma unroll
    for (int f = 0; f < 8; f++)
        #pragma unroll
        for (int j = 0; j < 4; j++) o[f][j] = 0.f;
    float m0r = -1e30f, m1r = -1e30f, l0r = 0.f, l1r = 0.f;

    const int NT = NL / 64;
    for (int t = 0; t < NT; t++) {
        cp_wait1();
        __syncthreads();
        const uint32_t base = skv + (uint32_t)(t & 1) * 32768u;

        float s[8][4];
        #pragma unroll
        for (int f = 0; f < 8; f++)
            #pragma unroll
            for (int j = 0; j < 4; j++) s[f][j] = 0.f;

        #pragma unroll
        for (int kc = 0; kc < 4; kc++) {
            uint32_t ah[4], al[4];
            {
                const int row = w * 16 + (lane & 15);
                const int chunk = 2 * kc + (lane >> 4);
                const uint32_t a = sq + (uint32_t)(row * 128 + ((chunk ^ (row & 7)) * 16));
                ldsm4(ah, a);
                ldsm4(al, a + 16384u);
            }
            #pragma unroll
            for (int g = 0; g < 4; g++) {
                uint32_t kh[4], kl[4];
                const int row = g * 16 + (lane & 15);
                const int chunk = 2 * kc + (lane >> 4);
                const uint32_t a = base + (uint32_t)(row * 128 + ((chunk ^ (row & 7)) * 16));
                ldsm4(kh, a);
                ldsm4(kl, a + 8192u);
                #pragma unroll
                for (int h2 = 0; h2 < 2; h2++) {
                    float* d = s[2 * g + h2];
                    mma16816(d, ah, kh[h2], kh[h2 + 2]);
                    mma16816(d, ah, kl[h2], kl[h2 + 2]);
                    mma16816(d, al, kh[h2], kh[h2 + 2]);
                }
            }
        }

        float mx0 = -1e30f, mx1 = -1e30f;
        #pragma unroll
        for (int f = 0; f < 8; f++) {
            mx0 = fmaxf(mx0, fmaxf(s[f][0], s[f][1]));
            mx1 = fmaxf(mx1, fmaxf(s[f][2], s[f][3]));
        }
        #pragma unroll
        for (int off = 1; off <= 2; off <<= 1) {
            mx0 = fmaxf(mx0, __shfl_xor_sync(0xffffffffu, mx0, off));
            mx1 = fmaxf(mx1, __shfl_xor_sync(0xffffffffu, mx1, off));
        }
        const float mn0 = fmaxf(m0r, mx0), mn1 = fmaxf(m1r, mx1);
        const float c0 = __expf(m0r - mn0), c1 = __expf(m1r - mn1);
        m0r = mn0; m1r = mn1;

        float su0 = 0.f, su1 = 0.f;
        #pragma unroll
        for (int f = 0; f < 8; f++) {
            s[f][0] = __expf(s[f][0] - mn0); su0 += s[f][0];
            s[f][1] = __expf(s[f][1] - mn0); su0 += s[f][1];
            s[f][2] = __expf(s[f][2] - mn1); su1 += s[f][2];
            s[f][3] = __expf(s[f][3] - mn1); su1 += s[f][3];
        }
        #pragma unroll
        for (int off = 1; off <= 2; off <<= 1) {
            su0 += __shfl_xor_sync(0xffffffffu, su0, off);
            su1 += __shfl_xor_sync(0xffffffffu, su1, off);
        }
        l0r = l0r * c0 + su0;
        l1r = l1r * c1 + su1;
        #pragma unroll
        for (int f = 0; f < 8; f++) {
            o[f][0] *= c0; o[f][1] *= c0;
            o[f][2] *= c1; o[f][3] *= c1;
        }

        #pragma unroll
        for (int kc = 0; kc < 4; kc++) {
            uint32_t ph[4], pl[4];
            split2(s[2*kc][0],   s[2*kc][1],   ph[0], pl[0]);
            split2(s[2*kc][2],   s[2*kc][3],   ph[1], pl[1]);
            split2(s[2*kc+1][0], s[2*kc+1][1], ph[2], pl[2]);
            split2(s[2*kc+1][2], s[2*kc+1][3], ph[3], pl[3]);
            #pragma unroll
            for (int g = 0; g < 4; g++) {
                uint32_t vh[4], vl[4];
                const int row = kc * 16 + (lane & 15);
                const int chunk = 2 * g + (lane >> 4);
                const uint32_t a = base + 16384u + (uint32_t)(row * 128 + ((chunk ^ (row & 7)) * 16));
                ldsm4t(vh, a);
                ldsm4t(vl, a + 8192u);
                mma16816(o[2*g],   ph, vh[0], vh[1]);
                mma16816(o[2*g],   ph, vl[0], vl[1]);
                mma16816(o[2*g],   pl, vh[0], vh[1]);
                mma16816(o[2*g+1], ph, vh[2], vh[3]);
                mma16816(o[2*g+1], ph, vl[2], vl[3]);
                mma16816(o[2*g+1], pl, vh[2], vh[3]);
            }
        }

        __syncthreads();
        if (t + 2 < NT) load_kv(t + 2, t & 1);
        cp_commit();
    }

    const float inv0 = 1.f / l0r, inv1 = 1.f / l1r;
    const int lr0 = q0 + w * 16 + (lane >> 2);
    #pragma unroll
    for (int f = 0; f < 8; f++) {
        const int d = f * 8 + (lane & 3) * 2;
        uint32_t hp, lp;
        split2(o[f][0] * inv0, o[f][1] * inv0, hp, lp);
        size_t idx = (((size_t)b * NL + lr0) * NH + h) * NHD + d;
        *(uint32_t*)(ohi + idx) = hp;
        *(uint32_t*)(olo + idx) = lp;
        split2(o[f][2] * inv1, o[f][3] * inv1, hp, lp);
        idx = (((size_t)b * NL + lr0 + 8) * NH + h) * NHD + d;
        *(uint32_t*)(ohi + idx) = hp;
        *(uint32_t*)(olo + idx) = lp;
    }
}

// ---------------------------------------------------------------------------
extern "C" void kernel_launch(void* const* d_in, const int* in_sizes, int n_in,
                              void* d_out, int out_size)
{
    (void)in_sizes; (void)n_in; (void)out_size;
    const float* x  = (const float*)d_in[0];
    const float* Wq = (const float*)d_in[1];
    const float* bq = (const float*)d_in[2];
    const float* Wk = (const float*)d_in[3];
    const float* bk = (const float*)d_in[4];
    const float* Wv = (const float*)d_in[5];
    const float* bv = (const float*)d_in[6];
    const float* Wo = (const float*)d_in[7];
    const float* bo = (const float*)d_in[8];

    __nv_bfloat16 *xhi, *xlo, *whi, *wlo, *ahi, *alo;
    __nv_bfloat16 *qhi, *qlo, *khi, *klo, *vhi, *vlo;
    cudaGetSymbolAddress((void**)&xhi, g_xhi);
    cudaGetSymbolAddress((void**)&xlo, g_xlo);
    cudaGetSymbolAddress((void**)&whi, g_whi);
    cudaGetSymbolAddress((void**)&wlo, g_wlo);
    cudaGetSymbolAddress((void**)&ahi, g_ahi);
    cudaGetSymbolAddress((void**)&alo, g_alo);
    cudaGetSymbolAddress((void**)&qhi, g_qhi);
    cudaGetSymbolAddress((void**)&qlo, g_qlo);
    cudaGetSymbolAddress((void**)&khi, g_khi);
    cudaGetSymbolAddress((void**)&klo, g_klo);
    cudaGetSymbolAddress((void**)&vhi, g_vhi);
    cudaGetSymbolAddress((void**)&vlo, g_vlo);

    rope_table_kernel<<<256, 256>>>();

    split8_kernel<<<(NM*NE/8 + 255)/256, 256>>>((const float4*)x, (uint4*)xhi, (uint4*)xlo, NM*NE/8);
    split8_kernel<<<(NW/8 + 255)/256, 256>>>((const float4*)Wq, (uint4*)(whi + 0*NW), (uint4*)(wlo + 0*NW), NW/8);
    split8_kernel<<<(NW/8 + 255)/256, 256>>>((const float4*)Wk, (uint4*)(whi + 1*NW), (uint4*)(wlo + 1*NW), NW/8);
    split8_kernel<<<(NW/8 + 255)/256, 256>>>((const float4*)Wv, (uint4*)(whi + 2*NW), (uint4*)(wlo + 2*NW), NW/8);
    split8_kernel<<<(NW/8 + 255)/256, 256>>>((const float4*)Wo, (uint4*)(whi + 3*NW), (uint4*)(wlo + 3*NW), NW/8);

    const int gsmem = 4 * 32768;   // 128 KB
    cudaFuncSetAttribute(qkv_gemm, cudaFuncAttributeMaxDynamicSharedMemorySize, gsmem);
    cudaFuncSetAttribute(out_gemm, cudaFuncAttributeMaxDynamicSharedMemorySize, gsmem);

    qkv_gemm<<<dim3(NE/128, NM/128, 3), 256, gsmem>>>(
        xhi, xlo, whi, wlo, bq, bk, bv, qhi, qlo, khi, klo, vhi, vlo);

    const int asmem = 32768 + 2 * 32768;   // 96 KB
    cudaFuncSetAttribute(attn_mma, cudaFuncAttributeMaxDynamicSharedMemorySize, asmem);
    attn_mma<<<dim3(NL/128, NB*NH), 256, asmem>>>(qhi, qlo, khi, klo, vhi, vlo, ahi, alo);

    out_gemm<<<dim3(NE/128, NM/128), 256, gsmem>>>(ahi, alo, whi + 3*NW, wlo + 3*NW, bo, (float*)d_out);
}

// round 7
// speedup vs baseline: 2.9751x; 1.1136x over previous
#include <cuda_runtime.h>
#include <cuda_bf16.h>
#include <math.h>
#include <stdint.h>

#define NB 2
#define NL 2048
#define NE 1024
#define NH 16
#define NHD 64
#define NM (NB*NL)   /* 4096 rows */
#define NW (NE*NE)

// ---------------- scratch (__device__ globals; no allocation) ----------------
__device__ __nv_bfloat16 g_xhi[NM*NE];
__device__ __nv_bfloat16 g_xlo[NM*NE];
__device__ __nv_bfloat16 g_whi[4*NE*NE];
__device__ __nv_bfloat16 g_wlo[4*NE*NE];
__device__ __nv_bfloat16 g_ahi[NM*NE];
__device__ __nv_bfloat16 g_alo[NM*NE];
__device__ __nv_bfloat16 g_qhi[NB*NH*NL*NHD];
__device__ __nv_bfloat16 g_qlo[NB*NH*NL*NHD];
__device__ __nv_bfloat16 g_khi[NB*NH*NL*NHD];
__device__ __nv_bfloat16 g_klo[NB*NH*NL*NHD];
__device__ __nv_bfloat16 g_vhi[NB*NH*NL*NHD];
__device__ __nv_bfloat16 g_vlo[NB*NH*NL*NHD];
__device__ float g_ctab[NL*32];
__device__ float g_stab[NL*32];

// ---------------- PTX helpers (sm_80-level only) ----------------
__device__ __forceinline__ uint32_t smem_u32(const void* p) {
    uint32_t a;
    asm("{ .reg .u64 t; cvta.to.shared.u64 t, %1; cvt.u32.u64 %0, t; }" : "=r"(a) : "l"(p));
    return a;
}
__device__ __forceinline__ void cp16(uint32_t s, const void* g) {
    asm volatile("cp.async.cg.shared.global [%0], [%1], 16;" :: "r"(s), "l"(g));
}
__device__ __forceinline__ void cp_commit() { asm volatile("cp.async.commit_group;" ::: "memory"); }
__device__ __forceinline__ void cp_wait1()  { asm volatile("cp.async.wait_group 1;" ::: "memory"); }

__device__ __forceinline__ void ldsm4(uint32_t* r, uint32_t addr) {
    asm volatile("ldmatrix.sync.aligned.m8n8.x4.shared.b16 {%0,%1,%2,%3}, [%4];"
                 : "=r"(r[0]), "=r"(r[1]), "=r"(r[2]), "=r"(r[3]) : "r"(addr));
}
__device__ __forceinline__ void ldsm4t(uint32_t* r, uint32_t addr) {
    asm volatile("ldmatrix.sync.aligned.m8n8.x4.trans.shared.b16 {%0,%1,%2,%3}, [%4];"
                 : "=r"(r[0]), "=r"(r[1]), "=r"(r[2]), "=r"(r[3]) : "r"(addr));
}
__device__ __forceinline__ void mma16816(float* d, const uint32_t* a, uint32_t b0, uint32_t b1) {
    asm volatile("mma.sync.aligned.m16n8k16.row.col.f32.bf16.bf16.f32 "
                 "{%0,%1,%2,%3}, {%4,%5,%6,%7}, {%8,%9}, {%0,%1,%2,%3};"
                 : "+f"(d[0]), "+f"(d[1]), "+f"(d[2]), "+f"(d[3])
                 : "r"(a[0]), "r"(a[1]), "r"(a[2]), "r"(a[3]), "r"(b0), "r"(b1));
}

__device__ __forceinline__ void split2(float x, float y, uint32_t& hp, uint32_t& lp) {
    __nv_bfloat16 hx = __float2bfloat16(x), hy = __float2bfloat16(y);
    float rx = x - __bfloat162float(hx), ry = y - __bfloat162float(hy);
    __nv_bfloat16 lx = __float2bfloat16(rx), ly = __float2bfloat16(ry);
    hp = (uint32_t)__bfloat16_as_ushort(hx) | ((uint32_t)__bfloat16_as_ushort(hy) << 16);
    lp = (uint32_t)__bfloat16_as_ushort(lx) | ((uint32_t)__bfloat16_as_ushort(ly) << 16);
}

// ---------------- RoPE cos/sin table: [l][d2], d2 = d/2 in 0..31 ----------------
__global__ void rope_table_kernel() {
    const int i = blockIdx.x * 256 + threadIdx.x;   // < 65536
    const int l = i >> 5, d2 = i & 31;
    const float invf = exp2f((float)d2 * (-13.287712379549449f / 32.0f));
    float sn, cs;
    sincosf((float)l * invf, &sn, &cs);
    g_ctab[i] = cs;
    g_stab[i] = sn;
}

// ---------------- vectorized split: 8 elements / thread ----------------
__global__ void split8_kernel(const float4* __restrict__ in,
                              uint4* __restrict__ hi, uint4* __restrict__ lo, int n8)
{
    const int i = blockIdx.x * blockDim.x + threadIdx.x;
    if (i >= n8) return;
    const float4 a = in[2*i], b = in[2*i + 1];
    uint32_t hw[4], lw[4];
    split2(a.x, a.y, hw[0], lw[0]);
    split2(a.z, a.w, hw[1], lw[1]);
    split2(b.x, b.y, hw[2], lw[2]);
    split2(b.z, b.w, hw[3], lw[3]);
    hi[i] = make_uint4(hw[0], hw[1], hw[2], hw[3]);
    lo[i] = make_uint4(lw[0], lw[1], lw[2], lw[3]);
}

// 4 weight matrices in one launch (grid.z selects source)
__global__ void splitw_kernel(const float4* __restrict__ w0, const float4* __restrict__ w1,
                              const float4* __restrict__ w2, const float4* __restrict__ w3,
                              uint4* __restrict__ hi, uint4* __restrict__ lo)
{
    const int z = blockIdx.z;
    const float4* in = (z == 0) ? w0 : (z == 1) ? w1 : (z == 2) ? w2 : w3;
    const int i = blockIdx.x * blockDim.x + threadIdx.x;
    if (i >= NW/8) return;
    const float4 a = in[2*i], b = in[2*i + 1];
    uint32_t hw[4], lw[4];
    split2(a.x, a.y, hw[0], lw[0]);
    split2(a.z, a.w, hw[1], lw[1]);
    split2(b.x, b.y, hw[2], lw[2]);
    split2(b.z, b.w, hw[3], lw[3]);
    hi[(size_t)z * (NW/8) + i] = make_uint4(hw[0], hw[1], hw[2], hw[3]);
    lo[(size_t)z * (NW/8) + i] = make_uint4(lw[0], lw[1], lw[2], lw[3]);
}

// ---------------------------------------------------------------------------
// Shared GEMM mainloop (CTA 128x128, BK=32, 8 warps 4x2, 3-stage cp.async).
// 96 KB smem -> 2 CTAs/SM. B fragments loaded per g-group to limit registers.
// ---------------------------------------------------------------------------
struct GemmCtx {
    float acc[2][8][4];
};

__device__ __forceinline__ void gemm_mainloop(
    const __nv_bfloat16* __restrict__ Ahi, const __nv_bfloat16* __restrict__ Alo,
    const __nv_bfloat16* __restrict__ Bhi, const __nv_bfloat16* __restrict__ Blo,
    int m0, int n0, uint32_t sm0, GemmCtx& cx)
{
    const int tid = threadIdx.x;
    const int lane = tid & 31, w = tid >> 5;
    const int wm = w & 3, wn = w >> 2;

    auto load_stage = [&](int stage, int buf) {
        const uint32_t base = sm0 + (uint32_t)buf * 32768u;
        const int kc = stage * 32;
        #pragma unroll
        for (int i = tid; i < 512; i += 256) {
            const int row = i >> 2, c = i & 3;
            const int cs = c ^ ((row >> 1) & 3);
            const uint32_t off = (uint32_t)(row * 64 + cs * 16);
            const size_t ga = (size_t)(m0 + row) * NE + kc + c * 8;
            const size_t gb = (size_t)(n0 + row) * NE + kc + c * 8;
            cp16(base +          off, Ahi + ga);
            cp16(base +  8192u + off, Alo + ga);
            cp16(base + 16384u + off, Bhi + gb);
            cp16(base + 24576u + off, Blo + gb);
        }
        cp_commit();
    };

    load_stage(0, 0); load_stage(1, 1);

    #pragma unroll
    for (int a = 0; a < 2; a++)
        #pragma unroll
        for (int b = 0; b < 8; b++)
            #pragma unroll
            for (int c = 0; c < 4; c++) cx.acc[a][b][c] = 0.f;

    const int NS = NE / 32;
    int buf = 0;                       // buffer of stage t (cycles 0,1,2)
    int nbuf = 2;                      // buffer for stage t+2
    for (int t = 0; t < NS; t++) {
        cp_wait1();
        __syncthreads();
        if (t + 2 < NS) load_stage(t + 2, nbuf); else cp_commit();

        const uint32_t base = sm0 + (uint32_t)buf * 32768u;
        #pragma unroll
        for (int s = 0; s < 2; s++) {
            const int chunk = 2 * s + (lane >> 4);
            uint32_t ah[2][4], al[2][4];
            #pragma unroll
            for (int mt = 0; mt < 2; mt++) {
                const int row = wm * 32 + mt * 16 + (lane & 15);
                const int cs = chunk ^ ((row >> 1) & 3);
                const uint32_t a = base + (uint32_t)(row * 64 + cs * 16);
                ldsm4(ah[mt], a);
                ldsm4(al[mt], a + 8192u);
            }
            #pragma unroll
            for (int g = 0; g < 4; g++) {
                uint32_t bh[4], bl[4];
                const int row = wn * 64 + g * 16 + (lane & 15);
                const int cs = chunk ^ ((row >> 1) & 3);
                const uint32_t a = base + 16384u + (uint32_t)(row * 64 + cs * 16);
                ldsm4(bh, a);
                ldsm4(bl, a + 8192u);
                #pragma unroll
                for (int mt = 0; mt < 2; mt++)
                    #pragma unroll
                    for (int h2 = 0; h2 < 2; h2++) {
                        float* d = cx.acc[mt][g * 2 + h2];
                        mma16816(d, ah[mt], bh[h2], bh[h2 + 2]);
                        mma16816(d, ah[mt], bl[h2], bl[h2 + 2]);
                        mma16816(d, al[mt], bh[h2], bh[h2 + 2]);
                    }
            }
        }
        __syncthreads();
        buf = (buf + 1 == 3) ? 0 : buf + 1;
        nbuf = (nbuf + 1 == 3) ? 0 : nbuf + 1;
    }
}

// ---------------------------------------------------------------------------
// Fused QKV projection. grid (8, 32, 3); z: 0=q (RoPE+0.125), 1=k (RoPE), 2=v.
// ---------------------------------------------------------------------------
__global__ __launch_bounds__(256, 2)
void qkv_gemm(const __nv_bfloat16* __restrict__ xhi, const __nv_bfloat16* __restrict__ xlo,
              const __nv_bfloat16* __restrict__ whi, const __nv_bfloat16* __restrict__ wlo,
              const float* __restrict__ bq, const float* __restrict__ bk,
              const float* __restrict__ bv,
              __nv_bfloat16* __restrict__ qhi, __nv_bfloat16* __restrict__ qlo,
              __nv_bfloat16* __restrict__ khi, __nv_bfloat16* __restrict__ klo,
              __nv_bfloat16* __restrict__ vhi, __nv_bfloat16* __restrict__ vlo)
{
    extern __shared__ char smraw[];
    const uint32_t sm0 = smem_u32(smraw);
    const int z = blockIdx.z;
    const int m0 = blockIdx.y * 128, n0 = blockIdx.x * 128;

    const float* bias = (z == 0) ? bq : (z == 1) ? bk : bv;
    __nv_bfloat16* OH = (z == 0) ? qhi : (z == 1) ? khi : vhi;
    __nv_bfloat16* OL = (z == 0) ? qlo : (z == 1) ? klo : vlo;

    GemmCtx cx;
    gemm_mainloop(xhi, xlo, whi + (size_t)z * NW, wlo + (size_t)z * NW, m0, n0, sm0, cx);

    const int lane = threadIdx.x & 31, w = threadIdx.x >> 5;
    const int wm = w & 3, wn = w >> 2;

    #pragma unroll
    for (int mt = 0; mt < 2; mt++) {
        #pragma unroll
        for (int f = 0; f < 8; f++) {
            const int colg = n0 + wn * 64 + f * 8 + (lane & 3) * 2;   // even
            const int h = colg >> 6, d = colg & 63;
            const int d2 = d >> 1;
            #pragma unroll
            for (int half = 0; half < 2; half++) {
                const int m = m0 + wm * 32 + mt * 16 + (lane >> 2) + half * 8;
                float v0 = cx.acc[mt][f][half * 2 + 0] + bias[colg];
                float v1 = cx.acc[mt][f][half * 2 + 1] + bias[colg + 1];
                const int bidx = m >> 11;
                const int l = m & (NL - 1);
                if (z < 2) {
                    const float cs = __ldg(&g_ctab[l * 32 + d2]);
                    const float sn = __ldg(&g_stab[l * 32 + d2]);
                    float r0 = v0 * cs - v1 * sn;
                    float r1 = v1 * cs + v0 * sn;
                    if (z == 0) { r0 *= 0.125f; r1 *= 0.125f; }
                    v0 = r0; v1 = r1;
                }
                uint32_t hp, lp;
                split2(v0, v1, hp, lp);
                const size_t idx = ((((size_t)bidx * NH + h) * NL) + l) * NHD + d;
                *(uint32_t*)(OH + idx) = hp;
                *(uint32_t*)(OL + idx) = lp;
            }
        }
    }
}

// ---------------------------------------------------------------------------
// Output projection: fp32 [m,n] + bias
// ---------------------------------------------------------------------------
__global__ __launch_bounds__(256, 2)
void out_gemm(const __nv_bfloat16* __restrict__ Ahi, const __nv_bfloat16* __restrict__ Alo,
              const __nv_bfloat16* __restrict__ Bhi, const __nv_bfloat16* __restrict__ Blo,
              const float* __restrict__ bias, float* __restrict__ out)
{
    extern __shared__ char smraw[];
    const uint32_t sm0 = smem_u32(smraw);
    const int m0 = blockIdx.y * 128, n0 = blockIdx.x * 128;

    GemmCtx cx;
    gemm_mainloop(Ahi, Alo, Bhi, Blo, m0, n0, sm0, cx);

    const int lane = threadIdx.x & 31, w = threadIdx.x >> 5;
    const int wm = w & 3, wn = w >> 2;

    #pragma unroll
    for (int mt = 0; mt < 2; mt++) {
        #pragma unroll
        for (int f = 0; f < 8; f++) {
            const int colg = n0 + wn * 64 + f * 8 + (lane & 3) * 2;
            #pragma unroll
            for (int half = 0; half < 2; half++) {
                const int m = m0 + wm * 32 + mt * 16 + (lane >> 2) + half * 8;
                const float v0 = cx.acc[mt][f][half * 2 + 0] + bias[colg];
                const float v1 = cx.acc[mt][f][half * 2 + 1] + bias[colg + 1];
                *(float2*)&out[(size_t)m * NE + colg] = make_float2(v0, v1);
            }
        }
    }
}

// ---------------------------------------------------------------------------
// Tensor-core flash attention (unchanged from R6; 2 CTAs/SM).
// ---------------------------------------------------------------------------
__global__ __launch_bounds__(256, 2)
void attn_mma(const __nv_bfloat16* __restrict__ qhi, const __nv_bfloat16* __restrict__ qlo,
              const __nv_bfloat16* __restrict__ khi, const __nv_bfloat16* __restrict__ klo,
              const __nv_bfloat16* __restrict__ vhi, const __nv_bfloat16* __restrict__ vlo,
              __nv_bfloat16* __restrict__ ohi, __nv_bfloat16* __restrict__ olo)
{
    extern __shared__ char smraw[];
    const uint32_t sq  = smem_u32(smraw);
    const uint32_t skv = sq + 32768u;

    const int tid = threadIdx.x;
    const int lane = tid & 31, w = tid >> 5;
    const int q0 = blockIdx.x * 128;
    const int bh = blockIdx.y;
    const int b = bh >> 4, h = bh & 15;
    const size_t kvbase_g = (size_t)bh * NL * NHD;

    #pragma unroll
    for (int i = tid; i < 1024; i += 256) {
        const int row = i >> 3, c = i & 7;
        const uint32_t off = (uint32_t)(row * 128 + ((c ^ (row & 7)) * 16));
        const size_t g = kvbase_g + (size_t)(q0 + row) * NHD + c * 8;
        cp16(sq + off, qhi + g);
        cp16(sq + 16384u + off, qlo + g);
    }

    auto load_kv = [&](int kt, int buf) {
        const uint32_t base = skv + (uint32_t)buf * 32768u;
        #pragma unroll
        for (int i = tid; i < 512; i += 256) {
            const int row = i >> 3, c = i & 7;
            const uint32_t off = (uint32_t)(row * 128 + ((c ^ (row & 7)) * 16));
            const size_t g = kvbase_g + (size_t)(kt * 64 + row) * NHD + c * 8;
            cp16(base +          off, khi + g);
            cp16(base +  8192u + off, klo + g);
            cp16(base + 16384u + off, vhi + g);
            cp16(base + 24576u + off, vlo + g);
        }
    };

    load_kv(0, 0); cp_commit();
    load_kv(1, 1); cp_commit();

    float o[8][4];
    #pragma unroll
    for (int f = 0; f < 8; f++)
        #pragma unroll
        for (int j = 0; j < 4; j++) o[f][j] = 0.f;
    float m0r = -1e30f, m1r = -1e30f, l0r = 0.f, l1r = 0.f;

    const int NT = NL / 64;
    for (int t = 0; t < NT; t++) {
        cp_wait1();
        __syncthreads();
        const uint32_t base = skv + (uint32_t)(t & 1) * 32768u;

        float s[8][4];
        #pragma unroll
        for (int f = 0; f < 8; f++)
            #pragma unroll
            for (int j = 0; j < 4; j++) s[f][j] = 0.f;

        #pragma unroll
        for (int kc = 0; kc < 4; kc++) {
            uint32_t ah[4], al[4];
            {
                const int row = w * 16 + (lane & 15);
                const int chunk = 2 * kc + (lane >> 4);
                const uint32_t a = sq + (uint32_t)(row * 128 + ((chunk ^ (row & 7)) * 16));
                ldsm4(ah, a);
                ldsm4(al, a + 16384u);
            }
            #pragma unroll
            for (int g = 0; g < 4; g++) {
                uint32_t kh[4], kl[4];
                const int row = g * 16 + (lane & 15);
                const int chunk = 2 * kc + (lane >> 4);
                const uint32_t a = base + (uint32_t)(row * 128 + ((chunk ^ (row & 7)) * 16));
                ldsm4(kh, a);
                ldsm4(kl, a + 8192u);
                #pragma unroll
                for (int h2 = 0; h2 < 2; h2++) {
                    float* d = s[2 * g + h2];
                    mma16816(d, ah, kh[h2], kh[h2 + 2]);
                    mma16816(d, ah, kl[h2], kl[h2 + 2]);
                    mma16816(d, al, kh[h2], kh[h2 + 2]);
                }
            }
        }

        float mx0 = -1e30f, mx1 = -1e30f;
        #pragma unroll
        for (int f = 0; f < 8; f++) {
            mx0 = fmaxf(mx0, fmaxf(s[f][0], s[f][1]));
            mx1 = fmaxf(mx1, fmaxf(s[f][2], s[f][3]));
        }
        #pragma unroll
        for (int off = 1; off <= 2; off <<= 1) {
            mx0 = fmaxf(mx0, __shfl_xor_sync(0xffffffffu, mx0, off));
            mx1 = fmaxf(mx1, __shfl_xor_sync(0xffffffffu, mx1, off));
        }
        const float mn0 = fmaxf(m0r, mx0), mn1 = fmaxf(m1r, mx1);
        const float c0 = __expf(m0r - mn0), c1 = __expf(m1r - mn1);
        m0r = mn0; m1r = mn1;

        float su0 = 0.f, su1 = 0.f;
        #pragma unroll
        for (int f = 0; f < 8; f++) {
            s[f][0] = __expf(s[f][0] - mn0); su0 += s[f][0];
            s[f][1] = __expf(s[f][1] - mn0); su0 += s[f][1];
            s[f][2] = __expf(s[f][2] - mn1); su1 += s[f][2];
            s[f][3] = __expf(s[f][3] - mn1); su1 += s[f][3];
        }
        #pragma unroll
        for (int off = 1; off <= 2; off <<= 1) {
            su0 += __shfl_xor_sync(0xffffffffu, su0, off);
            su1 += __shfl_xor_sync(0xffffffffu, su1, off);
        }
        l0r = l0r * c0 + su0;
        l1r = l1r * c1 + su1;
        #pragma unroll
        for (int f = 0; f < 8; f++) {
            o[f][0] *= c0; o[f][1] *= c0;
            o[f][2] *= c1; o[f][3] *= c1;
        }

        #pragma unroll
        for (int kc = 0; kc < 4; kc++) {
            uint32_t ph[4], pl[4];
            split2(s[2*kc][0],   s[2*kc][1],   ph[0], pl[0]);
            split2(s[2*kc][2],   s[2*kc][3],   ph[1], pl[1]);
            split2(s[2*kc+1][0], s[2*kc+1][1], ph[2], pl[2]);
            split2(s[2*kc+1][2], s[2*kc+1][3], ph[3], pl[3]);
            #pragma unroll
            for (int g = 0; g < 4; g++) {
                uint32_t vh[4], vl[4];
                const int row = kc * 16 + (lane & 15);
                const int chunk = 2 * g + (lane >> 4);
                const uint32_t a = base + 16384u + (uint32_t)(row * 128 + ((chunk ^ (row & 7)) * 16));
                ldsm4t(vh, a);
                ldsm4t(vl, a + 8192u);
                mma16816(o[2*g],   ph, vh[0], vh[1]);
                mma16816(o[2*g],   ph, vl[0], vl[1]);
                mma16816(o[2*g],   pl, vh[0], vh[1]);
                mma16816(o[2*g+1], ph, vh[2], vh[3]);
                mma16816(o[2*g+1], ph, vl[2], vl[3]);
                mma16816(o[2*g+1], pl, vh[2], vh[3]);
            }
        }

        __syncthreads();
        if (t + 2 < NT) load_kv(t + 2, t & 1);
        cp_commit();
    }

    const float inv0 = 1.f / l0r, inv1 = 1.f / l1r;
    const int lr0 = q0 + w * 16 + (lane >> 2);
    #pragma unroll
    for (int f = 0; f < 8; f++) {
        const int d = f * 8 + (lane & 3) * 2;
        uint32_t hp, lp;
        split2(o[f][0] * inv0, o[f][1] * inv0, hp, lp);
        size_t idx = (((size_t)b * NL + lr0) * NH + h) * NHD + d;
        *(uint32_t*)(ohi + idx) = hp;
        *(uint32_t*)(olo + idx) = lp;
        split2(o[f][2] * inv1, o[f][3] * inv1, hp, lp);
        idx = (((size_t)b * NL + lr0 + 8) * NH + h) * NHD + d;
        *(uint32_t*)(ohi + idx) = hp;
        *(uint32_t*)(olo + idx) = lp;
    }
}

// ---------------------------------------------------------------------------
extern "C" void kernel_launch(void* const* d_in, const int* in_sizes, int n_in,
                              void* d_out, int out_size)
{
    (void)in_sizes; (void)n_in; (void)out_size;
    const float* x  = (const float*)d_in[0];
    const float* Wq = (const float*)d_in[1];
    const float* bq = (const float*)d_in[2];
    const float* Wk = (const float*)d_in[3];
    const float* bk = (const float*)d_in[4];
    const float* Wv = (const float*)d_in[5];
    const float* bv = (const float*)d_in[6];
    const float* Wo = (const float*)d_in[7];
    const float* bo = (const float*)d_in[8];

    __nv_bfloat16 *xhi, *xlo, *whi, *wlo, *ahi, *alo;
    __nv_bfloat16 *qhi, *qlo, *khi, *klo, *vhi, *vlo;
    cudaGetSymbolAddress((void**)&xhi, g_xhi);
    cudaGetSymbolAddress((void**)&xlo, g_xlo);
    cudaGetSymbolAddress((void**)&whi, g_whi);
    cudaGetSymbolAddress((void**)&wlo, g_wlo);
    cudaGetSymbolAddress((void**)&ahi, g_ahi);
    cudaGetSymbolAddress((void**)&alo, g_alo);
    cudaGetSymbolAddress((void**)&qhi, g_qhi);
    cudaGetSymbolAddress((void**)&qlo, g_qlo);
    cudaGetSymbolAddress((void**)&khi, g_khi);
    cudaGetSymbolAddress((void**)&klo, g_klo);
    cudaGetSymbolAddress((void**)&vhi, g_vhi);
    cudaGetSymbolAddress((void**)&vlo, g_vlo);

    rope_table_kernel<<<256, 256>>>();

    split8_kernel<<<(NM*NE/8 + 255)/256, 256>>>((const float4*)x, (uint4*)xhi, (uint4*)xlo, NM*NE/8);
    splitw_kernel<<<dim3((NW/8 + 255)/256, 1, 4), 256>>>(
        (const float4*)Wq, (const float4*)Wk, (const float4*)Wv, (const float4*)Wo,
        (uint4*)whi, (uint4*)wlo);

    const int gsmem = 3 * 32768;   // 96 KB -> 2 CTAs/SM
    cudaFuncSetAttribute(qkv_gemm, cudaFuncAttributeMaxDynamicSharedMemorySize, gsmem);
    cudaFuncSetAttribute(out_gemm, cudaFuncAttributeMaxDynamicSharedMemorySize, gsmem);

    qkv_gemm<<<dim3(NE/128, NM/128, 3), 256, gsmem>>>(
        xhi, xlo, whi, wlo, bq, bk, bv, qhi, qlo, khi, klo, vhi, vlo);

    const int asmem = 32768 + 2 * 32768;   // 96 KB
    cudaFuncSetAttribute(attn_mma, cudaFuncAttributeMaxDynamicSharedMemorySize, asmem);
    attn_mma<<<dim3(NL/128, NB*NH), 256, asmem>>>(qhi, qlo, khi, klo, vhi, vlo, ahi, alo);

    out_gemm<<<dim3(NE/128, NM/128), 256, gsmem>>>(ahi, alo, whi + 3*NW, wlo + 3*NW, bo, (float*)d_out);
}